// round 6
// baseline (speedup 1.0000x reference)
#include <cuda_runtime.h>
#include <cstdint>

// ---------------------------------------------------------------------------
// Problem constants
// ---------------------------------------------------------------------------
#define BATCH   1568
#define NTOK    64
#define CDIM    512
#define HEADS   16
#define HD      32
#define NW      49
#define MTOT    (BATCH * NTOK)          // 100352
#define QKVN    (3 * CDIM)              // 1536

// ---------------------------------------------------------------------------
// Device scratch (static globals: allocation-free per harness rules)
// ---------------------------------------------------------------------------
__device__ float g_qkv[(size_t)MTOT * QKVN];       // qkv projection output
__device__ float g_att[(size_t)MTOT * CDIM];       // attention output (B,N,C)
__device__ float g_bm[HEADS * NW * NTOK * NTOK];   // fused bias+mask (h,w,64,64)
__device__ float g_tbl[225 * HEADS];               // CRPB table
__device__ float g_scale[HEADS];                   // clamped temperature per head

// ---------------------------------------------------------------------------
// tf32 / mma / cp.async helpers
// ---------------------------------------------------------------------------
__device__ __forceinline__ uint32_t f2tf32(float x) {
    uint32_t r;
    asm("cvt.rna.tf32.f32 %0, %1;" : "=r"(r) : "f"(x));
    return r;
}

__device__ __forceinline__ void mma_tf32(float* c, const uint32_t* a, const uint32_t* b) {
    asm volatile(
        "mma.sync.aligned.m16n8k8.row.col.f32.tf32.tf32.f32 "
        "{%0,%1,%2,%3}, {%4,%5,%6,%7}, {%8,%9}, {%0,%1,%2,%3};"
        : "+f"(c[0]), "+f"(c[1]), "+f"(c[2]), "+f"(c[3])
        : "r"(a[0]), "r"(a[1]), "r"(a[2]), "r"(a[3]),
          "r"(b[0]), "r"(b[1]));
}

__device__ __forceinline__ void ldsm_x4(uint32_t* r, const uint32_t* p) {
    uint32_t addr = (uint32_t)__cvta_generic_to_shared(p);
    asm volatile("ldmatrix.sync.aligned.m8n8.x4.shared.b16 {%0,%1,%2,%3}, [%4];"
                 : "=r"(r[0]), "=r"(r[1]), "=r"(r[2]), "=r"(r[3]) : "r"(addr));
}

__device__ __forceinline__ void cp16(uint32_t saddr, const void* g) {
    asm volatile("cp.async.ca.shared.global [%0], [%1], 16;" :: "r"(saddr), "l"(g));
}
__device__ __forceinline__ void cp_commit() {
    asm volatile("cp.async.commit_group;");
}
template <int N>
__device__ __forceinline__ void cp_wait() {
    asm volatile("cp.async.wait_group %0;" :: "n"(N));
}

// ---------------------------------------------------------------------------
// Kernel 1a: CRPB MLP table + temperature scale
// ---------------------------------------------------------------------------
__global__ void crpb_tbl_kernel(const float* __restrict__ ct,
                                const float* __restrict__ w1,
                                const float* __restrict__ b1,
                                const float* __restrict__ w2,
                                const float* __restrict__ ts)
{
    int e = threadIdx.x;
    if (e < HEADS) {
        g_scale[e] = expf(fminf(ts[e], 4.6051701859880913680f));
    }
    if (e < 225) {
        float c0 = ct[e * 2 + 0];
        float c1 = ct[e * 2 + 1];
        float acc[HEADS];
#pragma unroll
        for (int h = 0; h < HEADS; h++) acc[h] = 0.f;
        for (int j = 0; j < 384; j++) {
            float hv = fmaxf(w1[j * 2 + 0] * c0 + w1[j * 2 + 1] * c1 + b1[j], 0.f);
#pragma unroll
            for (int h = 0; h < HEADS; h++) acc[h] += w2[h * 384 + j] * hv;
        }
#pragma unroll
        for (int h = 0; h < HEADS; h++) g_tbl[e * HEADS + h] = acc[h];
    }
}

// ---------------------------------------------------------------------------
// Kernel 1b: fused bias+mask table
// g_bm[h][w][ij] = 16*sigmoid(tbl[rel_index[ij]][h]) + mask[w][ij]
// ---------------------------------------------------------------------------
__global__ void bm_fill_kernel(const int* __restrict__ ridx,
                               const float* __restrict__ mask)
{
    int t = blockIdx.x * blockDim.x + threadIdx.x;   // < 16*49*4096
    int ij = t & 4095;
    int hw = t >> 12;          // h*NW + w
    int w  = hw % NW;
    int h  = hw / NW;
    float v = g_tbl[ridx[ij] * HEADS + h];
    g_bm[t] = 16.f / (1.f + __expf(-v)) + mask[w * 4096 + ij];
}

// ---------------------------------------------------------------------------
// Kernel 2/4: tf32 tensor-core GEMM  C[m][n] = sum_k A[m][k]*B[n][k] + bias[n]
// A: MxK row-major, B: NxK row-major (C = A @ B^T).
// Block tile 128x128, K-tile 32, 256 threads = 8 warps (2m x 4n),
// warp tile 64x32 via m16n8k8 tf32 mma.sync.
// 3-stage cp.async pipeline, smem [row][k] fp32 with XOR-16B swizzle,
// ldmatrix.x4 fragment loads, tf32 conversion applied to fragment registers.
// M % 128 == 0, N % 128 == 0, K % 32 == 0.
// ---------------------------------------------------------------------------
#define BM 128
#define BN 128
#define BKT 32
#define STAGES 3
#define GEMM_SMEM (STAGES * (BM + BN) * BKT * 4)   // 98304 bytes

__global__ __launch_bounds__(256, 2)
void gemm_tf32_abT(const float* __restrict__ A, const float* __restrict__ B,
                   const float* __restrict__ bias, float* __restrict__ C,
                   int M, int N, int K)
{
    extern __shared__ uint32_t sm[];
    uint32_t* AsBase = sm;                          // [STAGES][BM][BKT]
    uint32_t* BsBase = sm + STAGES * BM * BKT;      // [STAGES][BN][BKT]
    const uint32_t smemA_u32 = (uint32_t)__cvta_generic_to_shared(AsBase);
    const uint32_t smemB_u32 = (uint32_t)__cvta_generic_to_shared(BsBase);

    const int tid  = threadIdx.x;
    const int bm   = blockIdx.y * BM;
    const int bn   = blockIdx.x * BN;
    const int warp = tid >> 5;
    const int lane = tid & 31;
    const int wm   = (warp & 1) * 64;
    const int wn   = (warp >> 1) * 32;
    const int g    = lane >> 2;
    const int t4   = lane & 3;

    // ldmatrix per-lane address decomposition
    const int lt = lane >> 3;
    const int lr = lane & 7;
    const int a_row_l = wm + (lt & 1) * 8 + lr;
    const int a_chk_l = lt >> 1;
    const int b_row_l = wn + (lt >> 1) * 8 + lr;
    const int b_chk_l = lt & 1;

    // global load assignment: 8 threads per row, fixed 16B chunk per thread
    const int row0   = tid >> 3;
    const int lchunk = tid & 7;

    float acc[4][4][4];
#pragma unroll
    for (int im = 0; im < 4; im++)
#pragma unroll
        for (int in = 0; in < 4; in++)
#pragma unroll
            for (int r = 0; r < 4; r++) acc[im][in][r] = 0.f;

    const int NIT = K / BKT;

    // issue loads for one k-tile into a stage
    auto issue = [&](int stage, int kt) {
        const int koff = kt * BKT + lchunk * 4;
#pragma unroll
        for (int l = 0; l < 4; l++) {
            int row = row0 + 32 * l;
            int sc  = (lchunk ^ (row & 7)) << 2;
            cp16(smemA_u32 + (uint32_t)(stage * BM * BKT + row * BKT + sc) * 4,
                 A + (size_t)(bm + row) * K + koff);
            cp16(smemB_u32 + (uint32_t)(stage * BN * BKT + row * BKT + sc) * 4,
                 B + (size_t)(bn + row) * K + koff);
        }
    };

    // prologue: stages 0 and 1
    issue(0, 0); cp_commit();
    issue(1, 1); cp_commit();

    for (int it = 0; it < NIT; it++) {
        const int s = it % STAGES;
        cp_wait<1>();
        __syncthreads();

        if (it + 2 < NIT) issue((it + 2) % STAGES, it + 2);
        cp_commit();

        const uint32_t* Ast = AsBase + s * BM * BKT;
        const uint32_t* Bst = BsBase + s * BN * BKT;
#pragma unroll
        for (int kk = 0; kk < BKT; kk += 8) {
            const int kc = kk >> 2;
            uint32_t af[4][4];
#pragma unroll
            for (int im = 0; im < 4; im++) {
                int row = a_row_l + im * 16;
                int chk = kc + a_chk_l;
                ldsm_x4(af[im], Ast + row * BKT + ((chk ^ (row & 7)) << 2));
#pragma unroll
                for (int r = 0; r < 4; r++)
                    af[im][r] = f2tf32(__uint_as_float(af[im][r]));
            }
            uint32_t bfr[8];
#pragma unroll
            for (int inp = 0; inp < 2; inp++) {
                int row = b_row_l + inp * 16;
                int chk = kc + b_chk_l;
                ldsm_x4(bfr + inp * 4, Bst + row * BKT + ((chk ^ (row & 7)) << 2));
#pragma unroll
                for (int r = 0; r < 4; r++)
                    bfr[inp * 4 + r] = f2tf32(__uint_as_float(bfr[inp * 4 + r]));
            }
#pragma unroll
            for (int im = 0; im < 4; im++)
#pragma unroll
                for (int in = 0; in < 4; in++)
                    mma_tf32(acc[im][in], af[im], bfr + in * 2);
        }
    }

    // epilogue
#pragma unroll
    for (int im = 0; im < 4; im++) {
#pragma unroll
        for (int in = 0; in < 4; in++) {
            int r = bm + wm + im * 16 + g;
            int c = bn + wn + in * 8 + t4 * 2;
            float b0 = bias[c];
            float b1 = bias[c + 1];
            float2 o0 = make_float2(acc[im][in][0] + b0, acc[im][in][1] + b1);
            float2 o1 = make_float2(acc[im][in][2] + b0, acc[im][in][3] + b1);
            *(float2*)(C + (size_t)r * N + c)       = o0;
            *(float2*)(C + (size_t)(r + 8) * N + c) = o1;
        }
    }
}

// ---------------------------------------------------------------------------
// Kernel 3: attention. One block per (window b, head h).
// All smem access vectorized float4, bias+mask fused, scale folded into Qn.
// ---------------------------------------------------------------------------
__global__ __launch_bounds__(256, 3)
void attn_kernel(float* __restrict__ out)
{
    const int bh = blockIdx.x;
    const int b  = bh >> 4;
    const int h  = bh & 15;
    const int w  = b % NW;

    __shared__ float Qs[64][36];
    __shared__ float Ks[64][36];
    __shared__ float Vs[64][36];
    __shared__ float Ss[64][68];

    const int tid = threadIdx.x;
    const float* base = g_qkv + (size_t)b * NTOK * QKVN + h * HD;

    // load Q, K, V tiles (float4)
#pragma unroll
    for (int l = 0; l < 2; l++) {
        int f = tid + l * 256;
        int t = f >> 3;
        int d = (f & 7) * 4;
        const float* rp = base + (size_t)t * QKVN;
        *(float4*)&Qs[t][d] = *(const float4*)(rp + 0 * CDIM + d);
        *(float4*)&Ks[t][d] = *(const float4*)(rp + 1 * CDIM + d);
        *(float4*)&Vs[t][d] = *(const float4*)(rp + 2 * CDIM + d);
    }
    __syncthreads();

    // cosine normalization (Q also folds the temperature scale)
    if (tid < 128) {
        int r = tid & 63;
        float* row = (tid < 64) ? Qs[r] : Ks[r];
        float s = 0.f;
        float4 c[8];
#pragma unroll
        for (int d4 = 0; d4 < 8; d4++) {
            c[d4] = *(float4*)&row[d4 * 4];
            s += c[d4].x * c[d4].x + c[d4].y * c[d4].y
               + c[d4].z * c[d4].z + c[d4].w * c[d4].w;
        }
        float inv = 1.0f / fmaxf(sqrtf(s), 1e-12f);
        if (tid < 64) inv *= g_scale[h];
#pragma unroll
        for (int d4 = 0; d4 < 8; d4++) {
            c[d4].x *= inv; c[d4].y *= inv; c[d4].z *= inv; c[d4].w *= inv;
            *(float4*)&row[d4 * 4] = c[d4];
        }
    }
    __syncthreads();

    // S = Qn Kn^T + (bias+mask); thread (tx,ty): rows ty*4+i, cols tx+16j
    {
        const int tx = tid & 15;
        const int ty = tid >> 4;
        const float* bmp = g_bm + (((size_t)h * NW + w) << 12);
        float s4[4][4];
#pragma unroll
        for (int i = 0; i < 4; i++)
#pragma unroll
            for (int j = 0; j < 4; j++) s4[i][j] = 0.f;
#pragma unroll
        for (int d4 = 0; d4 < 8; d4++) {
            float4 qa[4], kb[4];
#pragma unroll
            for (int i = 0; i < 4; i++) qa[i] = *(float4*)&Qs[ty * 4 + i][d4 * 4];
#pragma unroll
            for (int j = 0; j < 4; j++) kb[j] = *(float4*)&Ks[tx + 16 * j][d4 * 4];
#pragma unroll
            for (int i = 0; i < 4; i++)
#pragma unroll
                for (int j = 0; j < 4; j++)
                    s4[i][j] += qa[i].x * kb[j].x + qa[i].y * kb[j].y
                              + qa[i].z * kb[j].z + qa[i].w * kb[j].w;
        }
#pragma unroll
        for (int i = 0; i < 4; i++) {
            int r = ty * 4 + i;
#pragma unroll
            for (int j = 0; j < 4; j++) {
                int c = tx + 16 * j;
                Ss[r][c] = s4[i][j] + bmp[r * 64 + c];
            }
        }
    }
    __syncthreads();

    // row softmax: 8 warps x 8 rows, 2 cols per lane
    {
        const int wid  = tid >> 5;
        const int lane = tid & 31;
        for (int r = wid * 8; r < wid * 8 + 8; r++) {
            float v0 = Ss[r][lane];
            float v1 = Ss[r][lane + 32];
            float m = fmaxf(v0, v1);
#pragma unroll
            for (int off = 16; off > 0; off >>= 1)
                m = fmaxf(m, __shfl_xor_sync(0xffffffffu, m, off));
            float e0 = __expf(v0 - m);
            float e1 = __expf(v1 - m);
            float s = e0 + e1;
#pragma unroll
            for (int off = 16; off > 0; off >>= 1)
                s += __shfl_xor_sync(0xffffffffu, s, off);
            float inv = 1.0f / s;
            Ss[r][lane]      = e0 * inv;
            Ss[r][lane + 32] = e1 * inv;
        }
    }
    __syncthreads();

    // O = P V : thread (txc = tid&7, tyr = tid>>3): rows {tyr, tyr+32}, cols txc*4..+3
    {
        const int txc = tid & 7;
        const int tyr = tid >> 3;
        float4 o0 = make_float4(0.f, 0.f, 0.f, 0.f);
        float4 o1 = make_float4(0.f, 0.f, 0.f, 0.f);
#pragma unroll
        for (int jc = 0; jc < 16; jc++) {
            float4 p0 = *(float4*)&Ss[tyr][jc * 4];
            float4 p1 = *(float4*)&Ss[tyr + 32][jc * 4];
            float4 v0 = *(float4*)&Vs[jc * 4 + 0][txc * 4];
            float4 v1 = *(float4*)&Vs[jc * 4 + 1][txc * 4];
            float4 v2 = *(float4*)&Vs[jc * 4 + 2][txc * 4];
            float4 v3 = *(float4*)&Vs[jc * 4 + 3][txc * 4];
            o0.x += p0.x * v0.x + p0.y * v1.x + p0.z * v2.x + p0.w * v3.x;
            o0.y += p0.x * v0.y + p0.y * v1.y + p0.z * v2.y + p0.w * v3.y;
            o0.z += p0.x * v0.z + p0.y * v1.z + p0.z * v2.z + p0.w * v3.z;
            o0.w += p0.x * v0.w + p0.y * v1.w + p0.z * v2.w + p0.w * v3.w;
            o1.x += p1.x * v0.x + p1.y * v1.x + p1.z * v2.x + p1.w * v3.x;
            o1.y += p1.x * v0.y + p1.y * v1.y + p1.z * v2.y + p1.w * v3.y;
            o1.z += p1.x * v0.z + p1.y * v1.z + p1.z * v2.z + p1.w * v3.z;
            o1.w += p1.x * v0.w + p1.y * v1.w + p1.z * v2.w + p1.w * v3.w;
        }
        float* op0 = out + (size_t)(b * NTOK + tyr) * CDIM + h * HD + txc * 4;
        float* op1 = out + (size_t)(b * NTOK + tyr + 32) * CDIM + h * HD + txc * 4;
        *(float4*)op0 = o0;
        *(float4*)op1 = o1;
    }
}

// ---------------------------------------------------------------------------
// Launch
// ---------------------------------------------------------------------------
extern "C" void kernel_launch(void* const* d_in, const int* in_sizes, int n_in,
                              void* d_out, int out_size)
{
    const float* x        = (const float*)d_in[0];
    const float* mask     = (const float*)d_in[1];
    const float* qkv_w    = (const float*)d_in[2];
    const float* qkv_b    = (const float*)d_in[3];
    const float* proj_w   = (const float*)d_in[4];
    const float* proj_b   = (const float*)d_in[5];
    const float* t_scale  = (const float*)d_in[6];
    const float* crpb_w1  = (const float*)d_in[7];
    const float* crpb_b1  = (const float*)d_in[8];
    const float* crpb_w2  = (const float*)d_in[9];
    const float* ctable   = (const float*)d_in[10];
    const int*   rel_idx  = (const int*)d_in[11];
    float*       out      = (float*)d_out;

    float* qkv = nullptr;
    float* att = nullptr;
    cudaGetSymbolAddress((void**)&qkv, g_qkv);
    cudaGetSymbolAddress((void**)&att, g_att);

    static bool attr_set = false;
    if (!attr_set) {
        cudaFuncSetAttribute(gemm_tf32_abT,
                             cudaFuncAttributeMaxDynamicSharedMemorySize, GEMM_SMEM);
        cudaFuncSetAttribute(attn_kernel,
                             cudaFuncAttributePreferredSharedMemoryCarveout, 100);
        attr_set = true;
    }

    // 1. CRPB table + scale, fused bias+mask fill
    crpb_tbl_kernel<<<1, 256>>>(ctable, crpb_w1, crpb_b1, crpb_w2, t_scale);
    bm_fill_kernel<<<(HEADS * NW * 4096) / 256, 256>>>(rel_idx, mask);

    // 2. QKV projection: (100352 x 512) @ (1536 x 512)^T -> (100352 x 1536)
    {
        dim3 grid(QKVN / BN, MTOT / BM);
        gemm_tf32_abT<<<grid, 256, GEMM_SMEM>>>(x, qkv_w, qkv_b, qkv, MTOT, QKVN, CDIM);
    }

    // 3. attention: one block per (window, head)
    attn_kernel<<<BATCH * HEADS, 256>>>(att);

    // 4. output projection: (100352 x 512) @ (512 x 512)^T -> d_out
    {
        dim3 grid(CDIM / BN, MTOT / BM);
        gemm_tf32_abT<<<grid, 256, GEMM_SMEM>>>(att, proj_w, proj_b, out, MTOT, CDIM, CDIM);
    }
}

// round 7
// speedup vs baseline: 1.0289x; 1.0289x over previous
#include <cuda_runtime.h>
#include <cstdint>

// ---------------------------------------------------------------------------
// Problem constants
// ---------------------------------------------------------------------------
#define BATCH   1568
#define NTOK    64
#define CDIM    512
#define HEADS   16
#define HD      32
#define NW      49
#define MTOT    (BATCH * NTOK)          // 100352
#define QKVN    (3 * CDIM)              // 1536

// ---------------------------------------------------------------------------
// Device scratch (static globals: allocation-free per harness rules)
// ---------------------------------------------------------------------------
__device__ float g_qkv[(size_t)MTOT * QKVN];       // qkv projection output
__device__ float g_att[(size_t)MTOT * CDIM];       // attention output (tf32-rounded)
__device__ float g_x  [(size_t)MTOT * CDIM];       // tf32-rounded input x
__device__ float g_wq [(size_t)QKVN * CDIM];       // tf32-rounded qkv_w
__device__ float g_wp [(size_t)CDIM * CDIM];       // tf32-rounded proj_w
__device__ float g_bm [HEADS * NW * NTOK * NTOK];  // fused bias+mask (h,w,64,64)
__device__ float g_tbl[225 * HEADS];               // CRPB table
__device__ float g_scale[HEADS];                   // clamped temperature per head

// ---------------------------------------------------------------------------
// tf32 / mma / cp.async helpers
// ---------------------------------------------------------------------------
__device__ __forceinline__ uint32_t f2tf32(float x) {
    uint32_t r;
    asm("cvt.rna.tf32.f32 %0, %1;" : "=r"(r) : "f"(x));
    return r;
}

__device__ __forceinline__ void mma_tf32(float* c, const uint32_t* a, const uint32_t* b) {
    asm volatile(
        "mma.sync.aligned.m16n8k8.row.col.f32.tf32.tf32.f32 "
        "{%0,%1,%2,%3}, {%4,%5,%6,%7}, {%8,%9}, {%0,%1,%2,%3};"
        : "+f"(c[0]), "+f"(c[1]), "+f"(c[2]), "+f"(c[3])
        : "r"(a[0]), "r"(a[1]), "r"(a[2]), "r"(a[3]),
          "r"(b[0]), "r"(b[1]));
}

__device__ __forceinline__ void ldsm_x4(uint32_t* r, const uint32_t* p) {
    uint32_t addr = (uint32_t)__cvta_generic_to_shared(p);
    asm volatile("ldmatrix.sync.aligned.m8n8.x4.shared.b16 {%0,%1,%2,%3}, [%4];"
                 : "=r"(r[0]), "=r"(r[1]), "=r"(r[2]), "=r"(r[3]) : "r"(addr));
}

__device__ __forceinline__ void cp16(uint32_t saddr, const void* g) {
    asm volatile("cp.async.ca.shared.global [%0], [%1], 16;" :: "r"(saddr), "l"(g));
}
__device__ __forceinline__ void cp_commit() {
    asm volatile("cp.async.commit_group;");
}
template <int N>
__device__ __forceinline__ void cp_wait() {
    asm volatile("cp.async.wait_group %0;" :: "n"(N));
}

// ---------------------------------------------------------------------------
// Kernel 0: elementwise tf32 rounding (float4)
// ---------------------------------------------------------------------------
__global__ void round_tf32_kernel(const float* __restrict__ in,
                                  float* __restrict__ out, int n4)
{
    int i = blockIdx.x * blockDim.x + threadIdx.x;
    if (i >= n4) return;
    float4 v = ((const float4*)in)[i];
    v.x = __uint_as_float(f2tf32(v.x));
    v.y = __uint_as_float(f2tf32(v.y));
    v.z = __uint_as_float(f2tf32(v.z));
    v.w = __uint_as_float(f2tf32(v.w));
    ((float4*)out)[i] = v;
}

// ---------------------------------------------------------------------------
// Kernel 1a: CRPB MLP table + temperature scale
// ---------------------------------------------------------------------------
__global__ void crpb_tbl_kernel(const float* __restrict__ ct,
                                const float* __restrict__ w1,
                                const float* __restrict__ b1,
                                const float* __restrict__ w2,
                                const float* __restrict__ ts)
{
    int e = threadIdx.x;
    if (e < HEADS) {
        g_scale[e] = expf(fminf(ts[e], 4.6051701859880913680f));
    }
    if (e < 225) {
        float c0 = ct[e * 2 + 0];
        float c1 = ct[e * 2 + 1];
        float acc[HEADS];
#pragma unroll
        for (int h = 0; h < HEADS; h++) acc[h] = 0.f;
        for (int j = 0; j < 384; j++) {
            float hv = fmaxf(w1[j * 2 + 0] * c0 + w1[j * 2 + 1] * c1 + b1[j], 0.f);
#pragma unroll
            for (int h = 0; h < HEADS; h++) acc[h] += w2[h * 384 + j] * hv;
        }
#pragma unroll
        for (int h = 0; h < HEADS; h++) g_tbl[e * HEADS + h] = acc[h];
    }
}

// ---------------------------------------------------------------------------
// Kernel 1b: fused bias+mask table
// ---------------------------------------------------------------------------
__global__ void bm_fill_kernel(const int* __restrict__ ridx,
                               const float* __restrict__ mask)
{
    int t = blockIdx.x * blockDim.x + threadIdx.x;
    int ij = t & 4095;
    int hw = t >> 12;
    int w  = hw % NW;
    int h  = hw / NW;
    float v = g_tbl[ridx[ij] * HEADS + h];
    g_bm[t] = 16.f / (1.f + __expf(-v)) + mask[w * 4096 + ij];
}

// ---------------------------------------------------------------------------
// Kernel 2/4: tf32 tensor-core GEMM, inputs PRE-ROUNDED to tf32.
// C[m][n] = sum_k A[m][k]*B[n][k] + bias[n]; A: MxK, B: NxK row-major.
// Block 128x128, K-tile 32, 8 warps (2m x 4n), warp tile 64x32, m16n8k8.
// 3-stage cp.async pipeline; mainloop has ZERO cvt instructions.
// ---------------------------------------------------------------------------
#define BM 128
#define BN 128
#define BKT 32
#define STAGES 3
#define GEMM_SMEM (STAGES * (BM + BN) * BKT * 4)   // 98304 bytes

__global__ __launch_bounds__(256, 2)
void gemm_tf32_abT(const float* __restrict__ A, const float* __restrict__ B,
                   const float* __restrict__ bias, float* __restrict__ C,
                   int M, int N, int K)
{
    extern __shared__ uint32_t sm[];
    uint32_t* AsBase = sm;                          // [STAGES][BM][BKT]
    uint32_t* BsBase = sm + STAGES * BM * BKT;      // [STAGES][BN][BKT]
    const uint32_t smemA_u32 = (uint32_t)__cvta_generic_to_shared(AsBase);
    const uint32_t smemB_u32 = (uint32_t)__cvta_generic_to_shared(BsBase);

    const int tid  = threadIdx.x;
    const int bm   = blockIdx.y * BM;
    const int bn   = blockIdx.x * BN;
    const int warp = tid >> 5;
    const int lane = tid & 31;
    const int wm   = (warp & 1) * 64;
    const int wn   = (warp >> 1) * 32;
    const int g    = lane >> 2;
    const int t4   = lane & 3;

    const int lt = lane >> 3;
    const int lr = lane & 7;
    const int a_row_l = wm + (lt & 1) * 8 + lr;
    const int a_chk_l = lt >> 1;
    const int b_row_l = wn + (lt >> 1) * 8 + lr;
    const int b_chk_l = lt & 1;

    const int row0   = tid >> 3;
    const int lchunk = tid & 7;

    float acc[4][4][4];
#pragma unroll
    for (int im = 0; im < 4; im++)
#pragma unroll
        for (int in = 0; in < 4; in++)
#pragma unroll
            for (int r = 0; r < 4; r++) acc[im][in][r] = 0.f;

    const int NIT = K / BKT;

    auto issue = [&](int stage, int kt) {
        const int koff = kt * BKT + lchunk * 4;
#pragma unroll
        for (int l = 0; l < 4; l++) {
            int row = row0 + 32 * l;
            int sc  = (lchunk ^ (row & 7)) << 2;
            cp16(smemA_u32 + (uint32_t)(stage * BM * BKT + row * BKT + sc) * 4,
                 A + (size_t)(bm + row) * K + koff);
            cp16(smemB_u32 + (uint32_t)(stage * BN * BKT + row * BKT + sc) * 4,
                 B + (size_t)(bn + row) * K + koff);
        }
    };

    issue(0, 0); cp_commit();
    issue(1, 1); cp_commit();

    for (int it = 0; it < NIT; it++) {
        const int s = it % STAGES;
        cp_wait<1>();
        __syncthreads();

        if (it + 2 < NIT) issue((it + 2) % STAGES, it + 2);
        cp_commit();

        const uint32_t* Ast = AsBase + s * BM * BKT;
        const uint32_t* Bst = BsBase + s * BN * BKT;
#pragma unroll
        for (int kk = 0; kk < BKT; kk += 8) {
            const int kc = kk >> 2;
            uint32_t af[4][4];
#pragma unroll
            for (int im = 0; im < 4; im++) {
                int row = a_row_l + im * 16;
                int chk = kc + a_chk_l;
                ldsm_x4(af[im], Ast + row * BKT + ((chk ^ (row & 7)) << 2));
            }
            uint32_t bfr[8];
#pragma unroll
            for (int inp = 0; inp < 2; inp++) {
                int row = b_row_l + inp * 16;
                int chk = kc + b_chk_l;
                ldsm_x4(bfr + inp * 4, Bst + row * BKT + ((chk ^ (row & 7)) << 2));
            }
#pragma unroll
            for (int im = 0; im < 4; im++)
#pragma unroll
                for (int in = 0; in < 4; in++)
                    mma_tf32(acc[im][in], af[im], bfr + in * 2);
        }
    }

    // epilogue
#pragma unroll
    for (int im = 0; im < 4; im++) {
#pragma unroll
        for (int in = 0; in < 4; in++) {
            int r = bm + wm + im * 16 + g;
            int c = bn + wn + in * 8 + t4 * 2;
            float b0 = bias[c];
            float b1 = bias[c + 1];
            float2 o0 = make_float2(acc[im][in][0] + b0, acc[im][in][1] + b1);
            float2 o1 = make_float2(acc[im][in][2] + b0, acc[im][in][3] + b1);
            *(float2*)(C + (size_t)r * N + c)       = o0;
            *(float2*)(C + (size_t)(r + 8) * N + c) = o1;
        }
    }
}

// ---------------------------------------------------------------------------
// Kernel 3: attention. One block per (window b, head h).
// Output is tf32-rounded so the proj GEMM needs no conversion.
// ---------------------------------------------------------------------------
__global__ __launch_bounds__(256, 3)
void attn_kernel(float* __restrict__ out)
{
    const int bh = blockIdx.x;
    const int b  = bh >> 4;
    const int h  = bh & 15;
    const int w  = b % NW;

    __shared__ float Qs[64][36];
    __shared__ float Ks[64][36];
    __shared__ float Vs[64][36];
    __shared__ float Ss[64][68];

    const int tid = threadIdx.x;
    const float* base = g_qkv + (size_t)b * NTOK * QKVN + h * HD;

#pragma unroll
    for (int l = 0; l < 2; l++) {
        int f = tid + l * 256;
        int t = f >> 3;
        int d = (f & 7) * 4;
        const float* rp = base + (size_t)t * QKVN;
        *(float4*)&Qs[t][d] = *(const float4*)(rp + 0 * CDIM + d);
        *(float4*)&Ks[t][d] = *(const float4*)(rp + 1 * CDIM + d);
        *(float4*)&Vs[t][d] = *(const float4*)(rp + 2 * CDIM + d);
    }
    __syncthreads();

    if (tid < 128) {
        int r = tid & 63;
        float* row = (tid < 64) ? Qs[r] : Ks[r];
        float s = 0.f;
        float4 c[8];
#pragma unroll
        for (int d4 = 0; d4 < 8; d4++) {
            c[d4] = *(float4*)&row[d4 * 4];
            s += c[d4].x * c[d4].x + c[d4].y * c[d4].y
               + c[d4].z * c[d4].z + c[d4].w * c[d4].w;
        }
        float inv = 1.0f / fmaxf(sqrtf(s), 1e-12f);
        if (tid < 64) inv *= g_scale[h];
#pragma unroll
        for (int d4 = 0; d4 < 8; d4++) {
            c[d4].x *= inv; c[d4].y *= inv; c[d4].z *= inv; c[d4].w *= inv;
            *(float4*)&row[d4 * 4] = c[d4];
        }
    }
    __syncthreads();

    {
        const int tx = tid & 15;
        const int ty = tid >> 4;
        const float* bmp = g_bm + (((size_t)h * NW + w) << 12);
        float s4[4][4];
#pragma unroll
        for (int i = 0; i < 4; i++)
#pragma unroll
            for (int j = 0; j < 4; j++) s4[i][j] = 0.f;
#pragma unroll
        for (int d4 = 0; d4 < 8; d4++) {
            float4 qa[4], kb[4];
#pragma unroll
            for (int i = 0; i < 4; i++) qa[i] = *(float4*)&Qs[ty * 4 + i][d4 * 4];
#pragma unroll
            for (int j = 0; j < 4; j++) kb[j] = *(float4*)&Ks[tx + 16 * j][d4 * 4];
#pragma unroll
            for (int i = 0; i < 4; i++)
#pragma unroll
                for (int j = 0; j < 4; j++)
                    s4[i][j] += qa[i].x * kb[j].x + qa[i].y * kb[j].y
                              + qa[i].z * kb[j].z + qa[i].w * kb[j].w;
        }
#pragma unroll
        for (int i = 0; i < 4; i++) {
            int r = ty * 4 + i;
#pragma unroll
            for (int j = 0; j < 4; j++) {
                int c = tx + 16 * j;
                Ss[r][c] = s4[i][j] + bmp[r * 64 + c];
            }
        }
    }
    __syncthreads();

    {
        const int wid  = tid >> 5;
        const int lane = tid & 31;
        for (int r = wid * 8; r < wid * 8 + 8; r++) {
            float v0 = Ss[r][lane];
            float v1 = Ss[r][lane + 32];
            float m = fmaxf(v0, v1);
#pragma unroll
            for (int off = 16; off > 0; off >>= 1)
                m = fmaxf(m, __shfl_xor_sync(0xffffffffu, m, off));
            float e0 = __expf(v0 - m);
            float e1 = __expf(v1 - m);
            float s = e0 + e1;
#pragma unroll
            for (int off = 16; off > 0; off >>= 1)
                s += __shfl_xor_sync(0xffffffffu, s, off);
            float inv = 1.0f / s;
            Ss[r][lane]      = e0 * inv;
            Ss[r][lane + 32] = e1 * inv;
        }
    }
    __syncthreads();

    {
        const int txc = tid & 7;
        const int tyr = tid >> 3;
        float4 o0 = make_float4(0.f, 0.f, 0.f, 0.f);
        float4 o1 = make_float4(0.f, 0.f, 0.f, 0.f);
#pragma unroll
        for (int jc = 0; jc < 16; jc++) {
            float4 p0 = *(float4*)&Ss[tyr][jc * 4];
            float4 p1 = *(float4*)&Ss[tyr + 32][jc * 4];
            float4 v0 = *(float4*)&Vs[jc * 4 + 0][txc * 4];
            float4 v1 = *(float4*)&Vs[jc * 4 + 1][txc * 4];
            float4 v2 = *(float4*)&Vs[jc * 4 + 2][txc * 4];
            float4 v3 = *(float4*)&Vs[jc * 4 + 3][txc * 4];
            o0.x += p0.x * v0.x + p0.y * v1.x + p0.z * v2.x + p0.w * v3.x;
            o0.y += p0.x * v0.y + p0.y * v1.y + p0.z * v2.y + p0.w * v3.y;
            o0.z += p0.x * v0.z + p0.y * v1.z + p0.z * v2.z + p0.w * v3.z;
            o0.w += p0.x * v0.w + p0.y * v1.w + p0.z * v2.w + p0.w * v3.w;
            o1.x += p1.x * v0.x + p1.y * v1.x + p1.z * v2.x + p1.w * v3.x;
            o1.y += p1.x * v0.y + p1.y * v1.y + p1.z * v2.y + p1.w * v3.y;
            o1.z += p1.x * v0.z + p1.y * v1.z + p1.z * v2.z + p1.w * v3.z;
            o1.w += p1.x * v0.w + p1.y * v1.w + p1.z * v2.w + p1.w * v3.w;
        }
        // tf32-round the attention output so proj GEMM consumes it directly
        o0.x = __uint_as_float(f2tf32(o0.x)); o0.y = __uint_as_float(f2tf32(o0.y));
        o0.z = __uint_as_float(f2tf32(o0.z)); o0.w = __uint_as_float(f2tf32(o0.w));
        o1.x = __uint_as_float(f2tf32(o1.x)); o1.y = __uint_as_float(f2tf32(o1.y));
        o1.z = __uint_as_float(f2tf32(o1.z)); o1.w = __uint_as_float(f2tf32(o1.w));
        float* op0 = out + (size_t)(b * NTOK + tyr) * CDIM + h * HD + txc * 4;
        float* op1 = out + (size_t)(b * NTOK + tyr + 32) * CDIM + h * HD + txc * 4;
        *(float4*)op0 = o0;
        *(float4*)op1 = o1;
    }
}

// ---------------------------------------------------------------------------
// Launch
// ---------------------------------------------------------------------------
extern "C" void kernel_launch(void* const* d_in, const int* in_sizes, int n_in,
                              void* d_out, int out_size)
{
    const float* x        = (const float*)d_in[0];
    const float* mask     = (const float*)d_in[1];
    const float* qkv_w    = (const float*)d_in[2];
    const float* qkv_b    = (const float*)d_in[3];
    const float* proj_w   = (const float*)d_in[4];
    const float* proj_b   = (const float*)d_in[5];
    const float* t_scale  = (const float*)d_in[6];
    const float* crpb_w1  = (const float*)d_in[7];
    const float* crpb_b1  = (const float*)d_in[8];
    const float* crpb_w2  = (const float*)d_in[9];
    const float* ctable   = (const float*)d_in[10];
    const int*   rel_idx  = (const int*)d_in[11];
    float*       out      = (float*)d_out;

    float *qkv, *att, *xr, *wq, *wp;
    cudaGetSymbolAddress((void**)&qkv, g_qkv);
    cudaGetSymbolAddress((void**)&att, g_att);
    cudaGetSymbolAddress((void**)&xr,  g_x);
    cudaGetSymbolAddress((void**)&wq,  g_wq);
    cudaGetSymbolAddress((void**)&wp,  g_wp);

    static bool attr_set = false;
    if (!attr_set) {
        cudaFuncSetAttribute(gemm_tf32_abT,
                             cudaFuncAttributeMaxDynamicSharedMemorySize, GEMM_SMEM);
        cudaFuncSetAttribute(attn_kernel,
                             cudaFuncAttributePreferredSharedMemoryCarveout, 100);
        attr_set = true;
    }

    // 1. CRPB table + scale, fused bias+mask fill
    crpb_tbl_kernel<<<1, 256>>>(ctable, crpb_w1, crpb_b1, crpb_w2, t_scale);
    bm_fill_kernel<<<(HEADS * NW * 4096) / 256, 256>>>(rel_idx, mask);

    // 1b. pre-round GEMM operands to tf32
    {
        int n4x = MTOT * CDIM / 4;
        round_tf32_kernel<<<(n4x + 255) / 256, 256>>>(x, xr, n4x);
        int n4q = QKVN * CDIM / 4;
        round_tf32_kernel<<<(n4q + 255) / 256, 256>>>(qkv_w, wq, n4q);
        int n4p = CDIM * CDIM / 4;
        round_tf32_kernel<<<(n4p + 255) / 256, 256>>>(proj_w, wp, n4p);
    }

    // 2. QKV projection
    {
        dim3 grid(QKVN / BN, MTOT / BM);
        gemm_tf32_abT<<<grid, 256, GEMM_SMEM>>>(xr, wq, qkv_b, qkv, MTOT, QKVN, CDIM);
    }

    // 3. attention
    attn_kernel<<<BATCH * HEADS, 256>>>(att);

    // 4. output projection
    {
        dim3 grid(CDIM / BN, MTOT / BM);
        gemm_tf32_abT<<<grid, 256, GEMM_SMEM>>>(att, wp, proj_b, out, MTOT, CDIM, CDIM);
    }
}

// round 8
// speedup vs baseline: 1.4046x; 1.3652x over previous
#include <cuda_runtime.h>
#include <cuda_fp16.h>
#include <cstdint>

// ---------------------------------------------------------------------------
// Problem constants
// ---------------------------------------------------------------------------
#define BATCH   1568
#define NTOK    64
#define CDIM    512
#define HEADS   16
#define HD      32
#define NW      49
#define MTOT    (BATCH * NTOK)          // 100352
#define QKVN    (3 * CDIM)              // 1536

// ---------------------------------------------------------------------------
// Device scratch (static globals: allocation-free per harness rules)
// ---------------------------------------------------------------------------
__device__ float  g_qkv[(size_t)MTOT * QKVN];       // qkv projection output (fp32)
__device__ __half g_att[(size_t)MTOT * CDIM];       // attention output (fp16)
__device__ __half g_x  [(size_t)MTOT * CDIM];       // fp16 input x
__device__ __half g_wq [(size_t)QKVN * CDIM];       // fp16 qkv_w
__device__ __half g_wp [(size_t)CDIM * CDIM];       // fp16 proj_w
__device__ float  g_bm [HEADS * NW * NTOK * NTOK];  // fused bias+mask (h,w,64,64)
__device__ float  g_tbl[225 * HEADS];               // CRPB table
__device__ float  g_scale[HEADS];                   // clamped temperature per head

// ---------------------------------------------------------------------------
// mma / cp.async helpers
// ---------------------------------------------------------------------------
__device__ __forceinline__ void mma_f16(float* c, const uint32_t* a, const uint32_t* b) {
    asm volatile(
        "mma.sync.aligned.m16n8k16.row.col.f32.f16.f16.f32 "
        "{%0,%1,%2,%3}, {%4,%5,%6,%7}, {%8,%9}, {%0,%1,%2,%3};"
        : "+f"(c[0]), "+f"(c[1]), "+f"(c[2]), "+f"(c[3])
        : "r"(a[0]), "r"(a[1]), "r"(a[2]), "r"(a[3]),
          "r"(b[0]), "r"(b[1]));
}

__device__ __forceinline__ void ldsm_x4(uint32_t* r, const __half* p) {
    uint32_t addr = (uint32_t)__cvta_generic_to_shared(p);
    asm volatile("ldmatrix.sync.aligned.m8n8.x4.shared.b16 {%0,%1,%2,%3}, [%4];"
                 : "=r"(r[0]), "=r"(r[1]), "=r"(r[2]), "=r"(r[3]) : "r"(addr));
}

__device__ __forceinline__ void cp16(uint32_t saddr, const void* g) {
    asm volatile("cp.async.ca.shared.global [%0], [%1], 16;" :: "r"(saddr), "l"(g));
}
__device__ __forceinline__ void cp_commit() {
    asm volatile("cp.async.commit_group;");
}
template <int N>
__device__ __forceinline__ void cp_wait() {
    asm volatile("cp.async.wait_group %0;" :: "n"(N));
}

// ---------------------------------------------------------------------------
// Kernel 0: elementwise fp32 -> fp16 conversion (float4 -> 4 halves)
// ---------------------------------------------------------------------------
__global__ void to_half_kernel(const float* __restrict__ in,
                               __half* __restrict__ out, int n4)
{
    int i = blockIdx.x * blockDim.x + threadIdx.x;
    if (i >= n4) return;
    float4 v = ((const float4*)in)[i];
    __half2 h0 = __floats2half2_rn(v.x, v.y);
    __half2 h1 = __floats2half2_rn(v.z, v.w);
    ((__half2*)out)[i * 2 + 0] = h0;
    ((__half2*)out)[i * 2 + 1] = h1;
}

// ---------------------------------------------------------------------------
// Kernel 1a: CRPB MLP table + temperature scale
// ---------------------------------------------------------------------------
__global__ void crpb_tbl_kernel(const float* __restrict__ ct,
                                const float* __restrict__ w1,
                                const float* __restrict__ b1,
                                const float* __restrict__ w2,
                                const float* __restrict__ ts)
{
    int e = threadIdx.x;
    if (e < HEADS) {
        g_scale[e] = expf(fminf(ts[e], 4.6051701859880913680f));
    }
    if (e < 225) {
        float c0 = ct[e * 2 + 0];
        float c1 = ct[e * 2 + 1];
        float acc[HEADS];
#pragma unroll
        for (int h = 0; h < HEADS; h++) acc[h] = 0.f;
        for (int j = 0; j < 384; j++) {
            float hv = fmaxf(w1[j * 2 + 0] * c0 + w1[j * 2 + 1] * c1 + b1[j], 0.f);
#pragma unroll
            for (int h = 0; h < HEADS; h++) acc[h] += w2[h * 384 + j] * hv;
        }
#pragma unroll
        for (int h = 0; h < HEADS; h++) g_tbl[e * HEADS + h] = acc[h];
    }
}

// ---------------------------------------------------------------------------
// Kernel 1b: fused bias+mask table
// ---------------------------------------------------------------------------
__global__ void bm_fill_kernel(const int* __restrict__ ridx,
                               const float* __restrict__ mask)
{
    int t = blockIdx.x * blockDim.x + threadIdx.x;
    int ij = t & 4095;
    int hw = t >> 12;
    int w  = hw % NW;
    int h  = hw / NW;
    float v = g_tbl[ridx[ij] * HEADS + h];
    g_bm[t] = 16.f / (1.f + __expf(-v)) + mask[w * 4096 + ij];
}

// ---------------------------------------------------------------------------
// Kernel 2/4: fp16 tensor-core GEMM (fp32 accumulate).
// C[m][n] = sum_k A[m][k]*B[n][k] + bias[n]; A: MxK, B: NxK row-major fp16.
// Block 128x128, K-tile 64 halves (128B rows), 8 warps (2m x 4n),
// warp tile 64x32 via m16n8k16, 3-stage cp.async pipeline,
// XOR-16B swizzle (chunk ^ row&7), ldmatrix.x4 fragment loads.
// M % 128 == 0, N % 128 == 0, K % 64 == 0.
// ---------------------------------------------------------------------------
#define BM 128
#define BN 128
#define BKT 64
#define STAGES 3
#define GEMM_SMEM (STAGES * (BM + BN) * BKT * 2)   // 98304 bytes

__global__ __launch_bounds__(256, 2)
void gemm_f16_abT(const __half* __restrict__ A, const __half* __restrict__ B,
                  const float* __restrict__ bias, float* __restrict__ C,
                  int M, int N, int K)
{
    extern __shared__ __half smh[];
    __half* AsBase = smh;                           // [STAGES][BM][BKT]
    __half* BsBase = smh + STAGES * BM * BKT;       // [STAGES][BN][BKT]
    const uint32_t smemA_u32 = (uint32_t)__cvta_generic_to_shared(AsBase);
    const uint32_t smemB_u32 = (uint32_t)__cvta_generic_to_shared(BsBase);

    const int tid  = threadIdx.x;
    const int bm   = blockIdx.y * BM;
    const int bn   = blockIdx.x * BN;
    const int warp = tid >> 5;
    const int lane = tid & 31;
    const int wm   = (warp & 1) * 64;
    const int wn   = (warp >> 1) * 32;
    const int g    = lane >> 2;
    const int t4   = lane & 3;

    // ldmatrix lane decomposition (chunk = 8 halves = 16B)
    const int lt = lane >> 3;
    const int lr = lane & 7;
    const int a_row_l = wm + (lt & 1) * 8 + lr;   // + im*16
    const int a_chk_l = lt >> 1;                  // + 2*kstep
    const int b_row_l = wn + (lt >> 1) * 8 + lr;  // + n16*16
    const int b_chk_l = lt & 1;                   // + 2*kstep

    // global load: thread f handles row = f>>3, 16B chunk = f&7 (f = tid + 256l)
    float acc[4][4][4];
#pragma unroll
    for (int im = 0; im < 4; im++)
#pragma unroll
        for (int in = 0; in < 4; in++)
#pragma unroll
            for (int r = 0; r < 4; r++) acc[im][in][r] = 0.f;

    const int NIT = K / BKT;

    auto issue = [&](int stage, int kt) {
        const int kbase = kt * BKT;
#pragma unroll
        for (int l = 0; l < 4; l++) {
            int f    = tid + l * 256;     // 0..1023
            int row  = f >> 3;            // 0..127
            int chk  = f & 7;
            int sc   = (chk ^ (row & 7)) * 8;   // halves
            cp16(smemA_u32 + (uint32_t)(stage * BM * BKT + row * BKT + sc) * 2,
                 A + (size_t)(bm + row) * K + kbase + chk * 8);
            cp16(smemB_u32 + (uint32_t)(stage * BN * BKT + row * BKT + sc) * 2,
                 B + (size_t)(bn + row) * K + kbase + chk * 8);
        }
    };

    issue(0, 0); cp_commit();
    issue(1, 1); cp_commit();

    for (int it = 0; it < NIT; it++) {
        const int s = it % STAGES;
        cp_wait<1>();
        __syncthreads();

        if (it + 2 < NIT) issue((it + 2) % STAGES, it + 2);
        cp_commit();

        const __half* Ast = AsBase + s * BM * BKT;
        const __half* Bst = BsBase + s * BN * BKT;
#pragma unroll
        for (int ks = 0; ks < 4; ks++) {          // 4 k-steps of 16
            const int kc = ks * 2;
            uint32_t af[4][4];
#pragma unroll
            for (int im = 0; im < 4; im++) {
                int row = a_row_l + im * 16;
                int chk = kc + a_chk_l;
                ldsm_x4(af[im], Ast + row * BKT + ((chk ^ (row & 7)) * 8));
            }
            uint32_t bfr[8];
#pragma unroll
            for (int n16 = 0; n16 < 2; n16++) {
                int row = b_row_l + n16 * 16;
                int chk = kc + b_chk_l;
                ldsm_x4(bfr + n16 * 4, Bst + row * BKT + ((chk ^ (row & 7)) * 8));
            }
#pragma unroll
            for (int im = 0; im < 4; im++)
#pragma unroll
                for (int in = 0; in < 4; in++)
                    mma_f16(acc[im][in], af[im], bfr + in * 2);
        }
    }

    // epilogue (same C fragment layout as m16n8k8)
#pragma unroll
    for (int im = 0; im < 4; im++) {
#pragma unroll
        for (int in = 0; in < 4; in++) {
            int r = bm + wm + im * 16 + g;
            int c = bn + wn + in * 8 + t4 * 2;
            float b0 = bias[c];
            float b1 = bias[c + 1];
            float2 o0 = make_float2(acc[im][in][0] + b0, acc[im][in][1] + b1);
            float2 o1 = make_float2(acc[im][in][2] + b0, acc[im][in][3] + b1);
            *(float2*)(C + (size_t)r * N + c)       = o0;
            *(float2*)(C + (size_t)(r + 8) * N + c) = o1;
        }
    }
}

// ---------------------------------------------------------------------------
// Kernel 3: attention. One block per (window b, head h).
// Reads fp32 qkv, writes fp16 output for the proj GEMM.
// ---------------------------------------------------------------------------
__global__ __launch_bounds__(256, 3)
void attn_kernel(__half* __restrict__ out)
{
    const int bh = blockIdx.x;
    const int b  = bh >> 4;
    const int h  = bh & 15;
    const int w  = b % NW;

    __shared__ float Qs[64][36];
    __shared__ float Ks[64][36];
    __shared__ float Vs[64][36];
    __shared__ float Ss[64][68];

    const int tid = threadIdx.x;
    const float* base = g_qkv + (size_t)b * NTOK * QKVN + h * HD;

#pragma unroll
    for (int l = 0; l < 2; l++) {
        int f = tid + l * 256;
        int t = f >> 3;
        int d = (f & 7) * 4;
        const float* rp = base + (size_t)t * QKVN;
        *(float4*)&Qs[t][d] = *(const float4*)(rp + 0 * CDIM + d);
        *(float4*)&Ks[t][d] = *(const float4*)(rp + 1 * CDIM + d);
        *(float4*)&Vs[t][d] = *(const float4*)(rp + 2 * CDIM + d);
    }
    __syncthreads();

    if (tid < 128) {
        int r = tid & 63;
        float* row = (tid < 64) ? Qs[r] : Ks[r];
        float s = 0.f;
        float4 c[8];
#pragma unroll
        for (int d4 = 0; d4 < 8; d4++) {
            c[d4] = *(float4*)&row[d4 * 4];
            s += c[d4].x * c[d4].x + c[d4].y * c[d4].y
               + c[d4].z * c[d4].z + c[d4].w * c[d4].w;
        }
        float inv = 1.0f / fmaxf(sqrtf(s), 1e-12f);
        if (tid < 64) inv *= g_scale[h];
#pragma unroll
        for (int d4 = 0; d4 < 8; d4++) {
            c[d4].x *= inv; c[d4].y *= inv; c[d4].z *= inv; c[d4].w *= inv;
            *(float4*)&row[d4 * 4] = c[d4];
        }
    }
    __syncthreads();

    {
        const int tx = tid & 15;
        const int ty = tid >> 4;
        const float* bmp = g_bm + (((size_t)h * NW + w) << 12);
        float s4[4][4];
#pragma unroll
        for (int i = 0; i < 4; i++)
#pragma unroll
            for (int j = 0; j < 4; j++) s4[i][j] = 0.f;
#pragma unroll
        for (int d4 = 0; d4 < 8; d4++) {
            float4 qa[4], kb[4];
#pragma unroll
            for (int i = 0; i < 4; i++) qa[i] = *(float4*)&Qs[ty * 4 + i][d4 * 4];
#pragma unroll
            for (int j = 0; j < 4; j++) kb[j] = *(float4*)&Ks[tx + 16 * j][d4 * 4];
#pragma unroll
            for (int i = 0; i < 4; i++)
#pragma unroll
                for (int j = 0; j < 4; j++)
                    s4[i][j] += qa[i].x * kb[j].x + qa[i].y * kb[j].y
                              + qa[i].z * kb[j].z + qa[i].w * kb[j].w;
        }
#pragma unroll
        for (int i = 0; i < 4; i++) {
            int r = ty * 4 + i;
#pragma unroll
            for (int j = 0; j < 4; j++) {
                int c = tx + 16 * j;
                Ss[r][c] = s4[i][j] + bmp[r * 64 + c];
            }
        }
    }
    __syncthreads();

    {
        const int wid  = tid >> 5;
        const int lane = tid & 31;
        for (int r = wid * 8; r < wid * 8 + 8; r++) {
            float v0 = Ss[r][lane];
            float v1 = Ss[r][lane + 32];
            float m = fmaxf(v0, v1);
#pragma unroll
            for (int off = 16; off > 0; off >>= 1)
                m = fmaxf(m, __shfl_xor_sync(0xffffffffu, m, off));
            float e0 = __expf(v0 - m);
            float e1 = __expf(v1 - m);
            float s = e0 + e1;
#pragma unroll
            for (int off = 16; off > 0; off >>= 1)
                s += __shfl_xor_sync(0xffffffffu, s, off);
            float inv = 1.0f / s;
            Ss[r][lane]      = e0 * inv;
            Ss[r][lane + 32] = e1 * inv;
        }
    }
    __syncthreads();

    {
        const int txc = tid & 7;
        const int tyr = tid >> 3;
        float4 o0 = make_float4(0.f, 0.f, 0.f, 0.f);
        float4 o1 = make_float4(0.f, 0.f, 0.f, 0.f);
#pragma unroll
        for (int jc = 0; jc < 16; jc++) {
            float4 p0 = *(float4*)&Ss[tyr][jc * 4];
            float4 p1 = *(float4*)&Ss[tyr + 32][jc * 4];
            float4 v0 = *(float4*)&Vs[jc * 4 + 0][txc * 4];
            float4 v1 = *(float4*)&Vs[jc * 4 + 1][txc * 4];
            float4 v2 = *(float4*)&Vs[jc * 4 + 2][txc * 4];
            float4 v3 = *(float4*)&Vs[jc * 4 + 3][txc * 4];
            o0.x += p0.x * v0.x + p0.y * v1.x + p0.z * v2.x + p0.w * v3.x;
            o0.y += p0.x * v0.y + p0.y * v1.y + p0.z * v2.y + p0.w * v3.y;
            o0.z += p0.x * v0.z + p0.y * v1.z + p0.z * v2.z + p0.w * v3.z;
            o0.w += p0.x * v0.w + p0.y * v1.w + p0.z * v2.w + p0.w * v3.w;
            o1.x += p1.x * v0.x + p1.y * v1.x + p1.z * v2.x + p1.w * v3.x;
            o1.y += p1.x * v0.y + p1.y * v1.y + p1.z * v2.y + p1.w * v3.y;
            o1.z += p1.x * v0.z + p1.y * v1.z + p1.z * v2.z + p1.w * v3.z;
            o1.w += p1.x * v0.w + p1.y * v1.w + p1.z * v2.w + p1.w * v3.w;
        }
        __half2 h00 = __floats2half2_rn(o0.x, o0.y);
        __half2 h01 = __floats2half2_rn(o0.z, o0.w);
        __half2 h10 = __floats2half2_rn(o1.x, o1.y);
        __half2 h11 = __floats2half2_rn(o1.z, o1.w);
        __half2* op0 = (__half2*)(out + (size_t)(b * NTOK + tyr) * CDIM + h * HD + txc * 4);
        __half2* op1 = (__half2*)(out + (size_t)(b * NTOK + tyr + 32) * CDIM + h * HD + txc * 4);
        op0[0] = h00; op0[1] = h01;
        op1[0] = h10; op1[1] = h11;
    }
}

// ---------------------------------------------------------------------------
// Launch
// ---------------------------------------------------------------------------
extern "C" void kernel_launch(void* const* d_in, const int* in_sizes, int n_in,
                              void* d_out, int out_size)
{
    const float* x        = (const float*)d_in[0];
    const float* mask     = (const float*)d_in[1];
    const float* qkv_w    = (const float*)d_in[2];
    const float* qkv_b    = (const float*)d_in[3];
    const float* proj_w   = (const float*)d_in[4];
    const float* proj_b   = (const float*)d_in[5];
    const float* t_scale  = (const float*)d_in[6];
    const float* crpb_w1  = (const float*)d_in[7];
    const float* crpb_b1  = (const float*)d_in[8];
    const float* crpb_w2  = (const float*)d_in[9];
    const float* ctable   = (const float*)d_in[10];
    const int*   rel_idx  = (const int*)d_in[11];
    float*       out      = (float*)d_out;

    float  *qkv;
    __half *att, *xh, *wq, *wp;
    cudaGetSymbolAddress((void**)&qkv, g_qkv);
    cudaGetSymbolAddress((void**)&att, g_att);
    cudaGetSymbolAddress((void**)&xh,  g_x);
    cudaGetSymbolAddress((void**)&wq,  g_wq);
    cudaGetSymbolAddress((void**)&wp,  g_wp);

    static bool attr_set = false;
    if (!attr_set) {
        cudaFuncSetAttribute(gemm_f16_abT,
                             cudaFuncAttributeMaxDynamicSharedMemorySize, GEMM_SMEM);
        cudaFuncSetAttribute(attn_kernel,
                             cudaFuncAttributePreferredSharedMemoryCarveout, 100);
        attr_set = true;
    }

    // 1. CRPB table + scale, fused bias+mask fill
    crpb_tbl_kernel<<<1, 256>>>(ctable, crpb_w1, crpb_b1, crpb_w2, t_scale);
    bm_fill_kernel<<<(HEADS * NW * 4096) / 256, 256>>>(rel_idx, mask);

    // 1b. convert GEMM operands to fp16
    {
        int n4x = MTOT * CDIM / 4;
        to_half_kernel<<<(n4x + 255) / 256, 256>>>(x, xh, n4x);
        int n4q = QKVN * CDIM / 4;
        to_half_kernel<<<(n4q + 255) / 256, 256>>>(qkv_w, wq, n4q);
        int n4p = CDIM * CDIM / 4;
        to_half_kernel<<<(n4p + 255) / 256, 256>>>(proj_w, wp, n4p);
    }

    // 2. QKV projection: (100352 x 512) @ (1536 x 512)^T -> fp32
    {
        dim3 grid(QKVN / BN, MTOT / BM);
        gemm_f16_abT<<<grid, 256, GEMM_SMEM>>>(xh, wq, qkv_b, qkv, MTOT, QKVN, CDIM);
    }

    // 3. attention (fp32 in, fp16 out)
    attn_kernel<<<BATCH * HEADS, 256>>>(att);

    // 4. output projection: (100352 x 512) @ (512 x 512)^T -> d_out (fp32)
    {
        dim3 grid(CDIM / BN, MTOT / BM);
        gemm_f16_abT<<<grid, 256, GEMM_SMEM>>>(att, wp, proj_b, out, MTOT, CDIM, CDIM);
    }
}

// round 10
// speedup vs baseline: 2.0446x; 1.4556x over previous
#include <cuda_runtime.h>
#include <cuda_fp16.h>
#include <cstdint>
#include <cstring>

// ---------------------------------------------------------------------------
// Problem constants
// ---------------------------------------------------------------------------
#define BATCH   1568
#define NTOK    64
#define CDIM    512
#define HEADS   16
#define HD      32
#define NW      49
#define MTOT    (BATCH * NTOK)          // 100352
#define QKVN    (3 * CDIM)              // 1536

// ---------------------------------------------------------------------------
// Device scratch (static globals: allocation-free per harness rules)
// ---------------------------------------------------------------------------
__device__ __half g_qkvh[(size_t)MTOT * QKVN];      // qkv projection output (fp16)
__device__ __half g_att[(size_t)MTOT * CDIM];       // attention output (fp16)
__device__ __half g_x  [(size_t)MTOT * CDIM];       // fp16 input x
__device__ __half g_wq [(size_t)QKVN * CDIM];       // fp16 qkv_w
__device__ __half g_wp [(size_t)CDIM * CDIM];       // fp16 proj_w
__device__ float  g_bm [HEADS * NW * NTOK * NTOK];  // fused bias+mask (h,w,64,64)
__device__ float  g_tbl[225 * HEADS];               // CRPB table
__device__ float  g_scale[HEADS];                   // clamped temperature per head

// ---------------------------------------------------------------------------
// mma / cp.async helpers
// ---------------------------------------------------------------------------
__device__ __forceinline__ uint32_t h2_as_u32(__half2 h) {
    uint32_t u;
    memcpy(&u, &h, 4);
    return u;
}

__device__ __forceinline__ void mma_f16(float* c, const uint32_t* a, const uint32_t* b) {
    asm volatile(
        "mma.sync.aligned.m16n8k16.row.col.f32.f16.f16.f32 "
        "{%0,%1,%2,%3}, {%4,%5,%6,%7}, {%8,%9}, {%0,%1,%2,%3};"
        : "+f"(c[0]), "+f"(c[1]), "+f"(c[2]), "+f"(c[3])
        : "r"(a[0]), "r"(a[1]), "r"(a[2]), "r"(a[3]),
          "r"(b[0]), "r"(b[1]));
}

__device__ __forceinline__ void ldsm_x4(uint32_t* r, const __half* p) {
    uint32_t addr = (uint32_t)__cvta_generic_to_shared(p);
    asm volatile("ldmatrix.sync.aligned.m8n8.x4.shared.b16 {%0,%1,%2,%3}, [%4];"
                 : "=r"(r[0]), "=r"(r[1]), "=r"(r[2]), "=r"(r[3]) : "r"(addr));
}

__device__ __forceinline__ void ldsm_x4_trans(uint32_t* r, const __half* p) {
    uint32_t addr = (uint32_t)__cvta_generic_to_shared(p);
    asm volatile("ldmatrix.sync.aligned.m8n8.x4.trans.shared.b16 {%0,%1,%2,%3}, [%4];"
                 : "=r"(r[0]), "=r"(r[1]), "=r"(r[2]), "=r"(r[3]) : "r"(addr));
}

__device__ __forceinline__ void cp16(uint32_t saddr, const void* g) {
    asm volatile("cp.async.ca.shared.global [%0], [%1], 16;" :: "r"(saddr), "l"(g));
}
__device__ __forceinline__ void cp_commit() {
    asm volatile("cp.async.commit_group;");
}
template <int N>
__device__ __forceinline__ void cp_wait() {
    asm volatile("cp.async.wait_group %0;" :: "n"(N));
}

// ---------------------------------------------------------------------------
// Kernel 0: elementwise fp32 -> fp16 conversion
// ---------------------------------------------------------------------------
__global__ void to_half_kernel(const float* __restrict__ in,
                               __half* __restrict__ out, int n4)
{
    int i = blockIdx.x * blockDim.x + threadIdx.x;
    if (i >= n4) return;
    float4 v = ((const float4*)in)[i];
    ((__half2*)out)[i * 2 + 0] = __floats2half2_rn(v.x, v.y);
    ((__half2*)out)[i * 2 + 1] = __floats2half2_rn(v.z, v.w);
}

// ---------------------------------------------------------------------------
// Kernel 1a: CRPB MLP table + temperature scale
// ---------------------------------------------------------------------------
__global__ void crpb_tbl_kernel(const float* __restrict__ ct,
                                const float* __restrict__ w1,
                                const float* __restrict__ b1,
                                const float* __restrict__ w2,
                                const float* __restrict__ ts)
{
    int e = threadIdx.x;
    if (e < HEADS) {
        g_scale[e] = expf(fminf(ts[e], 4.6051701859880913680f));
    }
    if (e < 225) {
        float c0 = ct[e * 2 + 0];
        float c1 = ct[e * 2 + 1];
        float acc[HEADS];
#pragma unroll
        for (int h = 0; h < HEADS; h++) acc[h] = 0.f;
        for (int j = 0; j < 384; j++) {
            float hv = fmaxf(w1[j * 2 + 0] * c0 + w1[j * 2 + 1] * c1 + b1[j], 0.f);
#pragma unroll
            for (int h = 0; h < HEADS; h++) acc[h] += w2[h * 384 + j] * hv;
        }
#pragma unroll
        for (int h = 0; h < HEADS; h++) g_tbl[e * HEADS + h] = acc[h];
    }
}

// ---------------------------------------------------------------------------
// Kernel 1b: fused bias+mask table
// ---------------------------------------------------------------------------
__global__ void bm_fill_kernel(const int* __restrict__ ridx,
                               const float* __restrict__ mask)
{
    int t = blockIdx.x * blockDim.x + threadIdx.x;
    int ij = t & 4095;
    int hw = t >> 12;
    int w  = hw % NW;
    int h  = hw / NW;
    float v = g_tbl[ridx[ij] * HEADS + h];
    g_bm[t] = 16.f / (1.f + __expf(-v)) + mask[w * 4096 + ij];
}

// ---------------------------------------------------------------------------
// Kernel 2/4: fp16 tensor-core GEMM (fp32 accumulate), templated output type.
// C[m][n] = sum_k A[m][k]*B[n][k] + bias[n]; A: MxK, B: NxK row-major fp16.
// Block 128x128, K-tile 64 halves, 8 warps (2m x 4n), warp tile 64x32,
// m16n8k16, 3-stage cp.async pipeline, XOR-16B swizzle, ldmatrix.x4.
// ---------------------------------------------------------------------------
#define BM 128
#define BN 128
#define BKT 64
#define STAGES 3
#define GEMM_SMEM (STAGES * (BM + BN) * BKT * 2)   // 98304 bytes

template <typename OutT>
__global__ __launch_bounds__(256, 2)
void gemm_f16_abT(const __half* __restrict__ A, const __half* __restrict__ B,
                  const float* __restrict__ bias, OutT* __restrict__ C,
                  int M, int N, int K)
{
    extern __shared__ __half smh[];
    __half* AsBase = smh;
    __half* BsBase = smh + STAGES * BM * BKT;
    const uint32_t smemA_u32 = (uint32_t)__cvta_generic_to_shared(AsBase);
    const uint32_t smemB_u32 = (uint32_t)__cvta_generic_to_shared(BsBase);

    const int tid  = threadIdx.x;
    const int bm   = blockIdx.y * BM;
    const int bn   = blockIdx.x * BN;
    const int warp = tid >> 5;
    const int lane = tid & 31;
    const int wm   = (warp & 1) * 64;
    const int wn   = (warp >> 1) * 32;
    const int g    = lane >> 2;
    const int t4   = lane & 3;

    const int lt = lane >> 3;
    const int lr = lane & 7;
    const int a_row_l = wm + (lt & 1) * 8 + lr;
    const int a_chk_l = lt >> 1;
    const int b_row_l = wn + (lt >> 1) * 8 + lr;
    const int b_chk_l = lt & 1;

    float acc[4][4][4];
#pragma unroll
    for (int im = 0; im < 4; im++)
#pragma unroll
        for (int in = 0; in < 4; in++)
#pragma unroll
            for (int r = 0; r < 4; r++) acc[im][in][r] = 0.f;

    const int NIT = K / BKT;

    auto issue = [&](int stage, int kt) {
        const int kbase = kt * BKT;
#pragma unroll
        for (int l = 0; l < 4; l++) {
            int f    = tid + l * 256;
            int row  = f >> 3;
            int chk  = f & 7;
            int sc   = (chk ^ (row & 7)) * 8;
            cp16(smemA_u32 + (uint32_t)(stage * BM * BKT + row * BKT + sc) * 2,
                 A + (size_t)(bm + row) * K + kbase + chk * 8);
            cp16(smemB_u32 + (uint32_t)(stage * BN * BKT + row * BKT + sc) * 2,
                 B + (size_t)(bn + row) * K + kbase + chk * 8);
        }
    };

    issue(0, 0); cp_commit();
    issue(1, 1); cp_commit();

    for (int it = 0; it < NIT; it++) {
        const int s = it % STAGES;
        cp_wait<1>();
        __syncthreads();

        if (it + 2 < NIT) issue((it + 2) % STAGES, it + 2);
        cp_commit();

        const __half* Ast = AsBase + s * BM * BKT;
        const __half* Bst = BsBase + s * BN * BKT;
#pragma unroll
        for (int ks = 0; ks < 4; ks++) {
            const int kc = ks * 2;
            uint32_t af[4][4];
#pragma unroll
            for (int im = 0; im < 4; im++) {
                int row = a_row_l + im * 16;
                int chk = kc + a_chk_l;
                ldsm_x4(af[im], Ast + row * BKT + ((chk ^ (row & 7)) * 8));
            }
            uint32_t bfr[8];
#pragma unroll
            for (int n16 = 0; n16 < 2; n16++) {
                int row = b_row_l + n16 * 16;
                int chk = kc + b_chk_l;
                ldsm_x4(bfr + n16 * 4, Bst + row * BKT + ((chk ^ (row & 7)) * 8));
            }
#pragma unroll
            for (int im = 0; im < 4; im++)
#pragma unroll
                for (int in = 0; in < 4; in++)
                    mma_f16(acc[im][in], af[im], bfr + in * 2);
        }
    }

#pragma unroll
    for (int im = 0; im < 4; im++) {
#pragma unroll
        for (int in = 0; in < 4; in++) {
            int r = bm + wm + im * 16 + g;
            int c = bn + wn + in * 8 + t4 * 2;
            float b0 = bias[c];
            float b1 = bias[c + 1];
            float v00 = acc[im][in][0] + b0, v01 = acc[im][in][1] + b1;
            float v10 = acc[im][in][2] + b0, v11 = acc[im][in][3] + b1;
            if constexpr (sizeof(OutT) == 4) {
                *(float2*)((float*)C + (size_t)r * N + c)       = make_float2(v00, v01);
                *(float2*)((float*)C + (size_t)(r + 8) * N + c) = make_float2(v10, v11);
            } else {
                *(__half2*)((__half*)C + (size_t)r * N + c)       = __floats2half2_rn(v00, v01);
                *(__half2*)((__half*)C + (size_t)(r + 8) * N + c) = __floats2half2_rn(v10, v11);
            }
        }
    }
}

// ---------------------------------------------------------------------------
// Kernel 3: tensor-core attention. One block (128 thr, 4 warps) per (b,h).
// Warp w handles rows w*16..w*16+15 of the 64x64 score tile.
// S = QnKn^T via m16n8k16; softmax in registers; P reused as A-fragments
// for PV (ldmatrix.x4.trans on V). Reads/writes fp16.
// ---------------------------------------------------------------------------
__global__ __launch_bounds__(128)
void attn_mma_kernel(__half* __restrict__ out)
{
    const int bh = blockIdx.x;
    const int b  = bh >> 4;
    const int h  = bh & 15;
    const int w  = b % NW;

    __shared__ __half Qs[64][40];
    __shared__ __half Ks[64][40];
    __shared__ __half Vs[64][40];

    const int tid  = threadIdx.x;
    const int warp = tid >> 5;
    const int lane = tid & 31;

    // ---- load Q,K,V (fp16, 32 halves each per token) ----
    {
        const __half* base = g_qkvh + (size_t)b * NTOK * QKVN + h * HD;
        int tok = tid >> 1;
        int p   = tid & 1;          // which half of the 32-half row
        const uint4* qp = (const uint4*)(base + (size_t)tok * QKVN);        // q
        const uint4* kp = (const uint4*)(base + (size_t)tok * QKVN + 512);  // k
        const uint4* vp = (const uint4*)(base + (size_t)tok * QKVN + 1024); // v
        *(uint4*)&Qs[tok][p * 16 + 0] = qp[p * 2 + 0];
        *(uint4*)&Qs[tok][p * 16 + 8] = qp[p * 2 + 1];
        *(uint4*)&Ks[tok][p * 16 + 0] = kp[p * 2 + 0];
        *(uint4*)&Ks[tok][p * 16 + 8] = kp[p * 2 + 1];
        *(uint4*)&Vs[tok][p * 16 + 0] = vp[p * 2 + 0];
        *(uint4*)&Vs[tok][p * 16 + 8] = vp[p * 2 + 1];
    }
    __syncthreads();

    // ---- cosine normalization (Q folds temperature scale), fp32 math ----
    {
        int r = tid & 63;
        __half* row = (tid < 64) ? Qs[r] : Ks[r];
        float f[32];
        float s = 0.f;
#pragma unroll
        for (int i = 0; i < 16; i++) {
            float2 v = __half22float2(*(__half2*)&row[i * 2]);
            f[i * 2] = v.x; f[i * 2 + 1] = v.y;
            s += v.x * v.x + v.y * v.y;
        }
        float inv = 1.0f / fmaxf(sqrtf(s), 1e-12f);
        if (tid < 64) inv *= g_scale[h];
#pragma unroll
        for (int i = 0; i < 16; i++)
            *(__half2*)&row[i * 2] = __floats2half2_rn(f[i * 2] * inv, f[i * 2 + 1] * inv);
    }
    __syncthreads();

    const int lt = lane >> 3;
    const int lr = lane & 7;
    const int g  = lane >> 2;
    const int t4 = lane & 3;
    const int r0 = warp * 16;

    // ---- S = Qn Kn^T (this warp's 16 rows x 64 cols) ----
    float sacc[8][4];
#pragma unroll
    for (int t = 0; t < 8; t++)
#pragma unroll
        for (int r = 0; r < 4; r++) sacc[t][r] = 0.f;

#pragma unroll
    for (int ks = 0; ks < 2; ks++) {
        uint32_t af[4];
        ldsm_x4(af, &Qs[r0 + (lt & 1) * 8 + lr][(lt >> 1) * 8 + ks * 16]);
#pragma unroll
        for (int ng = 0; ng < 4; ng++) {
            uint32_t bf[4];
            ldsm_x4(bf, &Ks[ng * 16 + (lt >> 1) * 8 + lr][(lt & 1) * 8 + ks * 16]);
            mma_f16(sacc[ng * 2 + 0], af, bf);
            mma_f16(sacc[ng * 2 + 1], af, bf + 2);
        }
    }

    // ---- add bias+mask, softmax in registers ----
    const float* bmp = g_bm + (((size_t)h * NW + w) << 12);
    const int r_lo = r0 + g;
    const int r_hi = r0 + 8 + g;
#pragma unroll
    for (int t = 0; t < 8; t++) {
        int col = t * 8 + t4 * 2;
        float2 blo = *(const float2*)&bmp[r_lo * 64 + col];
        float2 bhi = *(const float2*)&bmp[r_hi * 64 + col];
        sacc[t][0] += blo.x; sacc[t][1] += blo.y;
        sacc[t][2] += bhi.x; sacc[t][3] += bhi.y;
    }

    float mlo = -1e30f, mhi = -1e30f;
#pragma unroll
    for (int t = 0; t < 8; t++) {
        mlo = fmaxf(mlo, fmaxf(sacc[t][0], sacc[t][1]));
        mhi = fmaxf(mhi, fmaxf(sacc[t][2], sacc[t][3]));
    }
    mlo = fmaxf(mlo, __shfl_xor_sync(0xffffffffu, mlo, 1));
    mlo = fmaxf(mlo, __shfl_xor_sync(0xffffffffu, mlo, 2));
    mhi = fmaxf(mhi, __shfl_xor_sync(0xffffffffu, mhi, 1));
    mhi = fmaxf(mhi, __shfl_xor_sync(0xffffffffu, mhi, 2));

    float slo = 0.f, shi = 0.f;
#pragma unroll
    for (int t = 0; t < 8; t++) {
        sacc[t][0] = __expf(sacc[t][0] - mlo);
        sacc[t][1] = __expf(sacc[t][1] - mlo);
        sacc[t][2] = __expf(sacc[t][2] - mhi);
        sacc[t][3] = __expf(sacc[t][3] - mhi);
        slo += sacc[t][0] + sacc[t][1];
        shi += sacc[t][2] + sacc[t][3];
    }
    slo += __shfl_xor_sync(0xffffffffu, slo, 1);
    slo += __shfl_xor_sync(0xffffffffu, slo, 2);
    shi += __shfl_xor_sync(0xffffffffu, shi, 1);
    shi += __shfl_xor_sync(0xffffffffu, shi, 2);
    const float ilo = 1.0f / slo;
    const float ihi = 1.0f / shi;

    // ---- P (fp16) in registers, laid out as PV A-fragments ----
    uint32_t p01[8], p23[8];
#pragma unroll
    for (int t = 0; t < 8; t++) {
        p01[t] = h2_as_u32(__floats2half2_rn(sacc[t][0] * ilo, sacc[t][1] * ilo));
        p23[t] = h2_as_u32(__floats2half2_rn(sacc[t][2] * ihi, sacc[t][3] * ihi));
    }

    // ---- O = P V (16 x 32) ----
    float oacc[4][4];
#pragma unroll
    for (int t = 0; t < 4; t++)
#pragma unroll
        for (int r = 0; r < 4; r++) oacc[t][r] = 0.f;

#pragma unroll
    for (int kg = 0; kg < 4; kg++) {
        uint32_t af[4] = { p01[kg * 2], p23[kg * 2], p01[kg * 2 + 1], p23[kg * 2 + 1] };
        uint32_t bf0[4], bf1[4];
        ldsm_x4_trans(bf0, &Vs[kg * 16 + (lt & 1) * 8 + lr][(lt >> 1) * 8]);
        ldsm_x4_trans(bf1, &Vs[kg * 16 + (lt & 1) * 8 + lr][(lt >> 1) * 8 + 16]);
        mma_f16(oacc[0], af, bf0);
        mma_f16(oacc[1], af, bf0 + 2);
        mma_f16(oacc[2], af, bf1);
        mma_f16(oacc[3], af, bf1 + 2);
    }

    // ---- write O (fp16) ----
    __half* ob = out + ((size_t)b * NTOK) * CDIM + h * HD;
#pragma unroll
    for (int t = 0; t < 4; t++) {
        int col = t * 8 + t4 * 2;
        *(__half2*)(ob + (size_t)r_lo * CDIM + col) = __floats2half2_rn(oacc[t][0], oacc[t][1]);
        *(__half2*)(ob + (size_t)r_hi * CDIM + col) = __floats2half2_rn(oacc[t][2], oacc[t][3]);
    }
}

// ---------------------------------------------------------------------------
// Launch
// ---------------------------------------------------------------------------
extern "C" void kernel_launch(void* const* d_in, const int* in_sizes, int n_in,
                              void* d_out, int out_size)
{
    const float* x        = (const float*)d_in[0];
    const float* mask     = (const float*)d_in[1];
    const float* qkv_w    = (const float*)d_in[2];
    const float* qkv_b    = (const float*)d_in[3];
    const float* proj_w   = (const float*)d_in[4];
    const float* proj_b   = (const float*)d_in[5];
    const float* t_scale  = (const float*)d_in[6];
    const float* crpb_w1  = (const float*)d_in[7];
    const float* crpb_b1  = (const float*)d_in[8];
    const float* crpb_w2  = (const float*)d_in[9];
    const float* ctable   = (const float*)d_in[10];
    const int*   rel_idx  = (const int*)d_in[11];
    float*       out      = (float*)d_out;

    __half *qkvh, *att, *xh, *wq, *wp;
    cudaGetSymbolAddress((void**)&qkvh, g_qkvh);
    cudaGetSymbolAddress((void**)&att,  g_att);
    cudaGetSymbolAddress((void**)&xh,   g_x);
    cudaGetSymbolAddress((void**)&wq,   g_wq);
    cudaGetSymbolAddress((void**)&wp,   g_wp);

    static bool attr_set = false;
    if (!attr_set) {
        cudaFuncSetAttribute(gemm_f16_abT<__half>,
                             cudaFuncAttributeMaxDynamicSharedMemorySize, GEMM_SMEM);
        cudaFuncSetAttribute(gemm_f16_abT<float>,
                             cudaFuncAttributeMaxDynamicSharedMemorySize, GEMM_SMEM);
        attr_set = true;
    }

    // 1. CRPB table + scale, fused bias+mask fill
    crpb_tbl_kernel<<<1, 256>>>(ctable, crpb_w1, crpb_b1, crpb_w2, t_scale);
    bm_fill_kernel<<<(HEADS * NW * 4096) / 256, 256>>>(rel_idx, mask);

    // 1b. convert GEMM operands to fp16
    {
        int n4x = MTOT * CDIM / 4;
        to_half_kernel<<<(n4x + 255) / 256, 256>>>(x, xh, n4x);
        int n4q = QKVN * CDIM / 4;
        to_half_kernel<<<(n4q + 255) / 256, 256>>>(qkv_w, wq, n4q);
        int n4p = CDIM * CDIM / 4;
        to_half_kernel<<<(n4p + 255) / 256, 256>>>(proj_w, wp, n4p);
    }

    // 2. QKV projection -> fp16
    {
        dim3 grid(QKVN / BN, MTOT / BM);
        gemm_f16_abT<__half><<<grid, 256, GEMM_SMEM>>>(xh, wq, qkv_b, qkvh, MTOT, QKVN, CDIM);
    }

    // 3. tensor-core attention (fp16 in/out)
    attn_mma_kernel<<<BATCH * HEADS, 128>>>(att);

    // 4. output projection -> fp32 d_out
    {
        dim3 grid(CDIM / BN, MTOT / BM);
        gemm_f16_abT<float><<<grid, 256, GEMM_SMEM>>>(att, wp, proj_b, out, MTOT, CDIM, CDIM);
    }
}

// round 12
// speedup vs baseline: 2.1188x; 1.0363x over previous
#include <cuda_runtime.h>
#include <cuda_fp16.h>
#include <cstdint>
#include <cstring>

// ---------------------------------------------------------------------------
// Problem constants
// ---------------------------------------------------------------------------
#define BATCH   1568
#define NTOK    64
#define CDIM    512
#define HEADS   16
#define HD      32
#define NW      49
#define MTOT    (BATCH * NTOK)          // 100352
#define QKVN    (3 * CDIM)              // 1536

// ---------------------------------------------------------------------------
// Device scratch (static globals: allocation-free per harness rules)
// ---------------------------------------------------------------------------
__device__ __half g_qkvh[(size_t)MTOT * QKVN];      // qkv projection output (fp16)
__device__ __half g_att[(size_t)MTOT * CDIM];       // attention output (fp16)
__device__ __half g_x  [(size_t)MTOT * CDIM];       // fp16 input x
__device__ __half g_wq [(size_t)QKVN * CDIM];       // fp16 qkv_w
__device__ __half g_wp [(size_t)CDIM * CDIM];       // fp16 proj_w
__device__ float  g_bm [HEADS * NW * NTOK * NTOK];  // fused bias+mask (h,w,64,64)
__device__ float  g_tbl[225 * HEADS];               // CRPB table
__device__ float  g_scale[HEADS];                   // clamped temperature per head

// ---------------------------------------------------------------------------
// helpers
// ---------------------------------------------------------------------------
__device__ __forceinline__ uint32_t h2_as_u32(__half2 h) {
    uint32_t u;
    memcpy(&u, &h, 4);
    return u;
}

__device__ __forceinline__ void mma_f16(float* c, const uint32_t* a, const uint32_t* b) {
    asm volatile(
        "mma.sync.aligned.m16n8k16.row.col.f32.f16.f16.f32 "
        "{%0,%1,%2,%3}, {%4,%5,%6,%7}, {%8,%9}, {%0,%1,%2,%3};"
        : "+f"(c[0]), "+f"(c[1]), "+f"(c[2]), "+f"(c[3])
        : "r"(a[0]), "r"(a[1]), "r"(a[2]), "r"(a[3]),
          "r"(b[0]), "r"(b[1]));
}

__device__ __forceinline__ void ldsm_x4(uint32_t* r, const __half* p) {
    uint32_t addr = (uint32_t)__cvta_generic_to_shared(p);
    asm volatile("ldmatrix.sync.aligned.m8n8.x4.shared.b16 {%0,%1,%2,%3}, [%4];"
                 : "=r"(r[0]), "=r"(r[1]), "=r"(r[2]), "=r"(r[3]) : "r"(addr));
}

__device__ __forceinline__ void ldsm_x4_trans(uint32_t* r, const __half* p) {
    uint32_t addr = (uint32_t)__cvta_generic_to_shared(p);
    asm volatile("ldmatrix.sync.aligned.m8n8.x4.trans.shared.b16 {%0,%1,%2,%3}, [%4];"
                 : "=r"(r[0]), "=r"(r[1]), "=r"(r[2]), "=r"(r[3]) : "r"(addr));
}

__device__ __forceinline__ void cp16(uint32_t saddr, const void* g) {
    asm volatile("cp.async.ca.shared.global [%0], [%1], 16;" :: "r"(saddr), "l"(g));
}
__device__ __forceinline__ void cp_commit() {
    asm volatile("cp.async.commit_group;");
}
template <int N>
__device__ __forceinline__ void cp_wait() {
    asm volatile("cp.async.wait_group %0;" :: "n"(N));
}

// ---------------------------------------------------------------------------
// Kernel 0: elementwise fp32 -> fp16 conversion
// ---------------------------------------------------------------------------
__global__ void to_half_kernel(const float* __restrict__ in,
                               __half* __restrict__ out, int n4)
{
    int i = blockIdx.x * blockDim.x + threadIdx.x;
    if (i >= n4) return;
    float4 v = ((const float4*)in)[i];
    ((__half2*)out)[i * 2 + 0] = __floats2half2_rn(v.x, v.y);
    ((__half2*)out)[i * 2 + 1] = __floats2half2_rn(v.z, v.w);
}

// ---------------------------------------------------------------------------
// Kernel 1a: CRPB MLP table + temperature scale
// ---------------------------------------------------------------------------
__global__ void crpb_tbl_kernel(const float* __restrict__ ct,
                                const float* __restrict__ w1,
                                const float* __restrict__ b1,
                                const float* __restrict__ w2,
                                const float* __restrict__ ts)
{
    int e = threadIdx.x;
    if (e < HEADS) {
        g_scale[e] = expf(fminf(ts[e], 4.6051701859880913680f));
    }
    if (e < 225) {
        float c0 = ct[e * 2 + 0];
        float c1 = ct[e * 2 + 1];
        float acc[HEADS];
#pragma unroll
        for (int h = 0; h < HEADS; h++) acc[h] = 0.f;
        for (int j = 0; j < 384; j++) {
            float hv = fmaxf(w1[j * 2 + 0] * c0 + w1[j * 2 + 1] * c1 + b1[j], 0.f);
#pragma unroll
            for (int h = 0; h < HEADS; h++) acc[h] += w2[h * 384 + j] * hv;
        }
#pragma unroll
        for (int h = 0; h < HEADS; h++) g_tbl[e * HEADS + h] = acc[h];
    }
}

// ---------------------------------------------------------------------------
// Kernel 1b: fused bias+mask table
// ---------------------------------------------------------------------------
__global__ void bm_fill_kernel(const int* __restrict__ ridx,
                               const float* __restrict__ mask)
{
    int t = blockIdx.x * blockDim.x + threadIdx.x;
    int ij = t & 4095;
    int hw = t >> 12;
    int w  = hw % NW;
    int h  = hw / NW;
    float v = g_tbl[ridx[ij] * HEADS + h];
    g_bm[t] = 16.f / (1.f + __expf(-v)) + mask[w * 4096 + ij];
}

// ---------------------------------------------------------------------------
// Kernel 2/4: fp16 mma.sync GEMM (fp32 accumulate), templated output type.
// C[m][n] = sum_k A[m][k]*B[n][k] + bias[n]; A: MxK, B: NxK row-major fp16.
// Block tile 128x128, K-tile 64 halves, 128 threads = 4 warps (2m x 2n),
// warp tile 64x64 (8 LDSM : 32 HMMA per k-step), m16n8k16,
// 3-stage cp.async pipeline, XOR-16B swizzle, ldmatrix.x4.
// ---------------------------------------------------------------------------
#define BM 128
#define BN 128
#define BKT 64
#define STAGES 3
#define GEMM_SMEM (STAGES * (BM + BN) * BKT * 2)   // 98304 bytes

template <typename OutT>
__global__ __launch_bounds__(128, 2)
void gemm_f16_abT(const __half* __restrict__ A, const __half* __restrict__ B,
                  const float* __restrict__ bias, OutT* __restrict__ C,
                  int M, int N, int K)
{
    extern __shared__ __half smh[];
    __half* AsBase = smh;
    __half* BsBase = smh + STAGES * BM * BKT;
    const uint32_t smemA_u32 = (uint32_t)__cvta_generic_to_shared(AsBase);
    const uint32_t smemB_u32 = (uint32_t)__cvta_generic_to_shared(BsBase);

    const int tid  = threadIdx.x;
    const int bm   = blockIdx.y * BM;
    const int bn   = blockIdx.x * BN;
    const int warp = tid >> 5;
    const int lane = tid & 31;
    const int wm   = (warp & 1) * 64;
    const int wn   = (warp >> 1) * 64;
    const int g    = lane >> 2;
    const int t4   = lane & 3;

    // ldmatrix lane decomposition (chunk = 8 halves = 16B)
    const int lt = lane >> 3;
    const int lr = lane & 7;
    const int a_row_l = wm + (lt & 1) * 8 + lr;   // + im*16
    const int a_chk_l = lt >> 1;                  // + 2*kstep
    const int b_row_l = wn + (lt >> 1) * 8 + lr;  // + n16*16
    const int b_chk_l = lt & 1;                   // + 2*kstep

    float acc[4][8][4];
#pragma unroll
    for (int im = 0; im < 4; im++)
#pragma unroll
        for (int in = 0; in < 8; in++)
#pragma unroll
            for (int r = 0; r < 4; r++) acc[im][in][r] = 0.f;

    const int NIT = K / BKT;

    auto issue = [&](int stage, int kt) {
        const int kbase = kt * BKT;
#pragma unroll
        for (int l = 0; l < 8; l++) {
            int f    = tid + l * 128;     // 0..1023
            int row  = f >> 3;            // 0..127
            int chk  = f & 7;
            int sc   = (chk ^ (row & 7)) * 8;
            cp16(smemA_u32 + (uint32_t)(stage * BM * BKT + row * BKT + sc) * 2,
                 A + (size_t)(bm + row) * K + kbase + chk * 8);
            cp16(smemB_u32 + (uint32_t)(stage * BN * BKT + row * BKT + sc) * 2,
                 B + (size_t)(bn + row) * K + kbase + chk * 8);
        }
    };

    issue(0, 0); cp_commit();
    issue(1, 1); cp_commit();

    for (int it = 0; it < NIT; it++) {
        const int s = it % STAGES;
        cp_wait<1>();
        __syncthreads();

        if (it + 2 < NIT) issue((it + 2) % STAGES, it + 2);
        cp_commit();

        const __half* Ast = AsBase + s * BM * BKT;
        const __half* Bst = BsBase + s * BN * BKT;
#pragma unroll
        for (int ks = 0; ks < 4; ks++) {          // 4 k-steps of 16
            const int kc = ks * 2;
            uint32_t af[4][4];
#pragma unroll
            for (int im = 0; im < 4; im++) {
                int row = a_row_l + im * 16;
                int chk = kc + a_chk_l;
                ldsm_x4(af[im], Ast + row * BKT + ((chk ^ (row & 7)) * 8));
            }
            uint32_t bfr[16];
#pragma unroll
            for (int n16 = 0; n16 < 4; n16++) {
                int row = b_row_l + n16 * 16;
                int chk = kc + b_chk_l;
                ldsm_x4(bfr + n16 * 4, Bst + row * BKT + ((chk ^ (row & 7)) * 8));
            }
#pragma unroll
            for (int im = 0; im < 4; im++)
#pragma unroll
                for (int in = 0; in < 8; in++)
                    mma_f16(acc[im][in], af[im], bfr + in * 2);
        }
    }

    // epilogue
#pragma unroll
    for (int im = 0; im < 4; im++) {
#pragma unroll
        for (int in = 0; in < 8; in++) {
            int r = bm + wm + im * 16 + g;
            int c = bn + wn + in * 8 + t4 * 2;
            float b0 = bias[c];
            float b1 = bias[c + 1];
            float v00 = acc[im][in][0] + b0, v01 = acc[im][in][1] + b1;
            float v10 = acc[im][in][2] + b0, v11 = acc[im][in][3] + b1;
            if constexpr (sizeof(OutT) == 4) {
                *(float2*)((float*)C + (size_t)r * N + c)       = make_float2(v00, v01);
                *(float2*)((float*)C + (size_t)(r + 8) * N + c) = make_float2(v10, v11);
            } else {
                *(__half2*)((__half*)C + (size_t)r * N + c)       = __floats2half2_rn(v00, v01);
                *(__half2*)((__half*)C + (size_t)(r + 8) * N + c) = __floats2half2_rn(v10, v11);
            }
        }
    }
}

// ---------------------------------------------------------------------------
// Kernel 3: tensor-core attention (unchanged from R10 passing version).
// ---------------------------------------------------------------------------
__global__ __launch_bounds__(128)
void attn_mma_kernel(__half* __restrict__ out)
{
    const int bh = blockIdx.x;
    const int b  = bh >> 4;
    const int h  = bh & 15;
    const int w  = b % NW;

    __shared__ __half Qs[64][40];
    __shared__ __half Ks[64][40];
    __shared__ __half Vs[64][40];

    const int tid  = threadIdx.x;
    const int warp = tid >> 5;
    const int lane = tid & 31;

    {
        const __half* base = g_qkvh + (size_t)b * NTOK * QKVN + h * HD;
        int tok = tid >> 1;
        int p   = tid & 1;
        const uint4* qp = (const uint4*)(base + (size_t)tok * QKVN);
        const uint4* kp = (const uint4*)(base + (size_t)tok * QKVN + 512);
        const uint4* vp = (const uint4*)(base + (size_t)tok * QKVN + 1024);
        *(uint4*)&Qs[tok][p * 16 + 0] = qp[p * 2 + 0];
        *(uint4*)&Qs[tok][p * 16 + 8] = qp[p * 2 + 1];
        *(uint4*)&Ks[tok][p * 16 + 0] = kp[p * 2 + 0];
        *(uint4*)&Ks[tok][p * 16 + 8] = kp[p * 2 + 1];
        *(uint4*)&Vs[tok][p * 16 + 0] = vp[p * 2 + 0];
        *(uint4*)&Vs[tok][p * 16 + 8] = vp[p * 2 + 1];
    }
    __syncthreads();

    {
        int r = tid & 63;
        __half* row = (tid < 64) ? Qs[r] : Ks[r];
        float f[32];
        float s = 0.f;
#pragma unroll
        for (int i = 0; i < 16; i++) {
            float2 v = __half22float2(*(__half2*)&row[i * 2]);
            f[i * 2] = v.x; f[i * 2 + 1] = v.y;
            s += v.x * v.x + v.y * v.y;
        }
        float inv = 1.0f / fmaxf(sqrtf(s), 1e-12f);
        if (tid < 64) inv *= g_scale[h];
#pragma unroll
        for (int i = 0; i < 16; i++)
            *(__half2*)&row[i * 2] = __floats2half2_rn(f[i * 2] * inv, f[i * 2 + 1] * inv);
    }
    __syncthreads();

    const int lt = lane >> 3;
    const int lr = lane & 7;
    const int g  = lane >> 2;
    const int t4 = lane & 3;
    const int r0 = warp * 16;

    float sacc[8][4];
#pragma unroll
    for (int t = 0; t < 8; t++)
#pragma unroll
        for (int r = 0; r < 4; r++) sacc[t][r] = 0.f;

#pragma unroll
    for (int ks = 0; ks < 2; ks++) {
        uint32_t af[4];
        ldsm_x4(af, &Qs[r0 + (lt & 1) * 8 + lr][(lt >> 1) * 8 + ks * 16]);
#pragma unroll
        for (int ng = 0; ng < 4; ng++) {
            uint32_t bf[4];
            ldsm_x4(bf, &Ks[ng * 16 + (lt >> 1) * 8 + lr][(lt & 1) * 8 + ks * 16]);
            mma_f16(sacc[ng * 2 + 0], af, bf);
            mma_f16(sacc[ng * 2 + 1], af, bf + 2);
        }
    }

    const float* bmp = g_bm + (((size_t)h * NW + w) << 12);
    const int r_lo = r0 + g;
    const int r_hi = r0 + 8 + g;
#pragma unroll
    for (int t = 0; t < 8; t++) {
        int col = t * 8 + t4 * 2;
        float2 blo = *(const float2*)&bmp[r_lo * 64 + col];
        float2 bhi = *(const float2*)&bmp[r_hi * 64 + col];
        sacc[t][0] += blo.x; sacc[t][1] += blo.y;
        sacc[t][2] += bhi.x; sacc[t][3] += bhi.y;
    }

    float mlo = -1e30f, mhi = -1e30f;
#pragma unroll
    for (int t = 0; t < 8; t++) {
        mlo = fmaxf(mlo, fmaxf(sacc[t][0], sacc[t][1]));
        mhi = fmaxf(mhi, fmaxf(sacc[t][2], sacc[t][3]));
    }
    mlo = fmaxf(mlo, __shfl_xor_sync(0xffffffffu, mlo, 1));
    mlo = fmaxf(mlo, __shfl_xor_sync(0xffffffffu, mlo, 2));
    mhi = fmaxf(mhi, __shfl_xor_sync(0xffffffffu, mhi, 1));
    mhi = fmaxf(mhi, __shfl_xor_sync(0xffffffffu, mhi, 2));

    float slo = 0.f, shi = 0.f;
#pragma unroll
    for (int t = 0; t < 8; t++) {
        sacc[t][0] = __expf(sacc[t][0] - mlo);
        sacc[t][1] = __expf(sacc[t][1] - mlo);
        sacc[t][2] = __expf(sacc[t][2] - mhi);
        sacc[t][3] = __expf(sacc[t][3] - mhi);
        slo += sacc[t][0] + sacc[t][1];
        shi += sacc[t][2] + sacc[t][3];
    }
    slo += __shfl_xor_sync(0xffffffffu, slo, 1);
    slo += __shfl_xor_sync(0xffffffffu, slo, 2);
    shi += __shfl_xor_sync(0xffffffffu, shi, 1);
    shi += __shfl_xor_sync(0xffffffffu, shi, 2);
    const float ilo = 1.0f / slo;
    const float ihi = 1.0f / shi;

    uint32_t p01[8], p23[8];
#pragma unroll
    for (int t = 0; t < 8; t++) {
        p01[t] = h2_as_u32(__floats2half2_rn(sacc[t][0] * ilo, sacc[t][1] * ilo));
        p23[t] = h2_as_u32(__floats2half2_rn(sacc[t][2] * ihi, sacc[t][3] * ihi));
    }

    float oacc[4][4];
#pragma unroll
    for (int t = 0; t < 4; t++)
#pragma unroll
        for (int r = 0; r < 4; r++) oacc[t][r] = 0.f;

#pragma unroll
    for (int kg = 0; kg < 4; kg++) {
        uint32_t af[4] = { p01[kg * 2], p23[kg * 2], p01[kg * 2 + 1], p23[kg * 2 + 1] };
        uint32_t bf0[4], bf1[4];
        ldsm_x4_trans(bf0, &Vs[kg * 16 + (lt & 1) * 8 + lr][(lt >> 1) * 8]);
        ldsm_x4_trans(bf1, &Vs[kg * 16 + (lt & 1) * 8 + lr][(lt >> 1) * 8 + 16]);
        mma_f16(oacc[0], af, bf0);
        mma_f16(oacc[1], af, bf0 + 2);
        mma_f16(oacc[2], af, bf1);
        mma_f16(oacc[3], af, bf1 + 2);
    }

    __half* ob = out + ((size_t)b * NTOK) * CDIM + h * HD;
#pragma unroll
    for (int t = 0; t < 4; t++) {
        int col = t * 8 + t4 * 2;
        *(__half2*)(ob + (size_t)r_lo * CDIM + col) = __floats2half2_rn(oacc[t][0], oacc[t][1]);
        *(__half2*)(ob + (size_t)r_hi * CDIM + col) = __floats2half2_rn(oacc[t][2], oacc[t][3]);
    }
}

// ---------------------------------------------------------------------------
// Launch
// ---------------------------------------------------------------------------
extern "C" void kernel_launch(void* const* d_in, const int* in_sizes, int n_in,
                              void* d_out, int out_size)
{
    const float* x        = (const float*)d_in[0];
    const float* mask     = (const float*)d_in[1];
    const float* qkv_w    = (const float*)d_in[2];
    const float* qkv_b    = (const float*)d_in[3];
    const float* proj_w   = (const float*)d_in[4];
    const float* proj_b   = (const float*)d_in[5];
    const float* t_scale  = (const float*)d_in[6];
    const float* crpb_w1  = (const float*)d_in[7];
    const float* crpb_b1  = (const float*)d_in[8];
    const float* crpb_w2  = (const float*)d_in[9];
    const float* ctable   = (const float*)d_in[10];
    const int*   rel_idx  = (const int*)d_in[11];
    float*       out      = (float*)d_out;

    __half *qkvh, *att, *xh, *wq, *wp;
    cudaGetSymbolAddress((void**)&qkvh, g_qkvh);
    cudaGetSymbolAddress((void**)&att,  g_att);
    cudaGetSymbolAddress((void**)&xh,   g_x);
    cudaGetSymbolAddress((void**)&wq,   g_wq);
    cudaGetSymbolAddress((void**)&wp,   g_wp);

    static bool attr_set = false;
    if (!attr_set) {
        cudaFuncSetAttribute(gemm_f16_abT<__half>,
                             cudaFuncAttributeMaxDynamicSharedMemorySize, GEMM_SMEM);
        cudaFuncSetAttribute(gemm_f16_abT<float>,
                             cudaFuncAttributeMaxDynamicSharedMemorySize, GEMM_SMEM);
        attr_set = true;
    }

    // 1. CRPB table + scale, fused bias+mask fill
    crpb_tbl_kernel<<<1, 256>>>(ctable, crpb_w1, crpb_b1, crpb_w2, t_scale);
    bm_fill_kernel<<<(HEADS * NW * 4096) / 256, 256>>>(rel_idx, mask);

    // 1b. convert GEMM operands to fp16
    {
        int n4x = MTOT * CDIM / 4;
        to_half_kernel<<<(n4x + 255) / 256, 256>>>(x, xh, n4x);
        int n4q = QKVN * CDIM / 4;
        to_half_kernel<<<(n4q + 255) / 256, 256>>>(qkv_w, wq, n4q);
        int n4p = CDIM * CDIM / 4;
        to_half_kernel<<<(n4p + 255) / 256, 256>>>(proj_w, wp, n4p);
    }

    // 2. QKV projection -> fp16
    {
        dim3 grid(QKVN / BN, MTOT / BM);
        gemm_f16_abT<__half><<<grid, 128, GEMM_SMEM>>>(xh, wq, qkv_b, qkvh, MTOT, QKVN, CDIM);
    }

    // 3. tensor-core attention (fp16 in/out)
    attn_mma_kernel<<<BATCH * HEADS, 128>>>(att);

    // 4. output projection -> fp32 d_out
    {
        dim3 grid(CDIM / BN, MTOT / BM);
        gemm_f16_abT<float><<<grid, 128, GEMM_SMEM>>>(att, wp, proj_b, out, MTOT, CDIM, CDIM);
    }
}

// round 13
// speedup vs baseline: 2.1216x; 1.0013x over previous
#include <cuda_runtime.h>
#include <cuda_fp16.h>
#include <cstdint>
#include <cstring>

// ---------------------------------------------------------------------------
// Problem constants
// ---------------------------------------------------------------------------
#define BATCH   1568
#define NTOK    64
#define CDIM    512
#define HEADS   16
#define HD      32
#define NW      49
#define MTOT    (BATCH * NTOK)          // 100352
#define QKVN    (3 * CDIM)              // 1536

// ---------------------------------------------------------------------------
// Device scratch (static globals: allocation-free per harness rules)
// ---------------------------------------------------------------------------
__device__ __half g_qkvh[(size_t)MTOT * QKVN];      // qkv projection output (fp16)
__device__ __half g_att[(size_t)MTOT * CDIM];       // attention output (fp16)
__device__ __half g_x  [(size_t)MTOT * CDIM];       // fp16 input x
__device__ __half g_wq [(size_t)QKVN * CDIM];       // fp16 qkv_w
__device__ __half g_wp [(size_t)CDIM * CDIM];       // fp16 proj_w
__device__ float  g_bm [HEADS * NW * NTOK * NTOK];  // fused bias+mask (h,w,64,64)
__device__ float  g_tbl[225 * HEADS];               // CRPB table
__device__ float  g_scale[HEADS];                   // clamped temperature per head

// ---------------------------------------------------------------------------
// helpers
// ---------------------------------------------------------------------------
__device__ __forceinline__ uint32_t h2_as_u32(__half2 h) {
    uint32_t u;
    memcpy(&u, &h, 4);
    return u;
}

__device__ __forceinline__ void mma_f16(float* c, const uint32_t* a, const uint32_t* b) {
    asm volatile(
        "mma.sync.aligned.m16n8k16.row.col.f32.f16.f16.f32 "
        "{%0,%1,%2,%3}, {%4,%5,%6,%7}, {%8,%9}, {%0,%1,%2,%3};"
        : "+f"(c[0]), "+f"(c[1]), "+f"(c[2]), "+f"(c[3])
        : "r"(a[0]), "r"(a[1]), "r"(a[2]), "r"(a[3]),
          "r"(b[0]), "r"(b[1]));
}

__device__ __forceinline__ void ldsm_x4(uint32_t* r, const __half* p) {
    uint32_t addr = (uint32_t)__cvta_generic_to_shared(p);
    asm volatile("ldmatrix.sync.aligned.m8n8.x4.shared.b16 {%0,%1,%2,%3}, [%4];"
                 : "=r"(r[0]), "=r"(r[1]), "=r"(r[2]), "=r"(r[3]) : "r"(addr));
}

__device__ __forceinline__ void ldsm_x4_trans(uint32_t* r, const __half* p) {
    uint32_t addr = (uint32_t)__cvta_generic_to_shared(p);
    asm volatile("ldmatrix.sync.aligned.m8n8.x4.trans.shared.b16 {%0,%1,%2,%3}, [%4];"
                 : "=r"(r[0]), "=r"(r[1]), "=r"(r[2]), "=r"(r[3]) : "r"(addr));
}

__device__ __forceinline__ void cp16(uint32_t saddr, const void* g) {
    asm volatile("cp.async.ca.shared.global [%0], [%1], 16;" :: "r"(saddr), "l"(g));
}
__device__ __forceinline__ void cp_commit() {
    asm volatile("cp.async.commit_group;");
}
template <int N>
__device__ __forceinline__ void cp_wait() {
    asm volatile("cp.async.wait_group %0;" :: "n"(N));
}

// ---------------------------------------------------------------------------
// Kernel 0: elementwise fp32 -> fp16 conversion
// ---------------------------------------------------------------------------
__global__ void to_half_kernel(const float* __restrict__ in,
                               __half* __restrict__ out, int n4)
{
    int i = blockIdx.x * blockDim.x + threadIdx.x;
    if (i >= n4) return;
    float4 v = ((const float4*)in)[i];
    ((__half2*)out)[i * 2 + 0] = __floats2half2_rn(v.x, v.y);
    ((__half2*)out)[i * 2 + 1] = __floats2half2_rn(v.z, v.w);
}

// ---------------------------------------------------------------------------
// Kernel 1a: CRPB MLP table + temperature scale
// ---------------------------------------------------------------------------
__global__ void crpb_tbl_kernel(const float* __restrict__ ct,
                                const float* __restrict__ w1,
                                const float* __restrict__ b1,
                                const float* __restrict__ w2,
                                const float* __restrict__ ts)
{
    int e = threadIdx.x;
    if (e < HEADS) {
        g_scale[e] = expf(fminf(ts[e], 4.6051701859880913680f));
    }
    if (e < 225) {
        float c0 = ct[e * 2 + 0];
        float c1 = ct[e * 2 + 1];
        float acc[HEADS];
#pragma unroll
        for (int h = 0; h < HEADS; h++) acc[h] = 0.f;
        for (int j = 0; j < 384; j++) {
            float hv = fmaxf(w1[j * 2 + 0] * c0 + w1[j * 2 + 1] * c1 + b1[j], 0.f);
#pragma unroll
            for (int h = 0; h < HEADS; h++) acc[h] += w2[h * 384 + j] * hv;
        }
#pragma unroll
        for (int h = 0; h < HEADS; h++) g_tbl[e * HEADS + h] = acc[h];
    }
}

// ---------------------------------------------------------------------------
// Kernel 1b: fused bias+mask table
// ---------------------------------------------------------------------------
__global__ void bm_fill_kernel(const int* __restrict__ ridx,
                               const float* __restrict__ mask)
{
    int t = blockIdx.x * blockDim.x + threadIdx.x;
    int ij = t & 4095;
    int hw = t >> 12;
    int w  = hw % NW;
    int h  = hw / NW;
    float v = g_tbl[ridx[ij] * HEADS + h];
    g_bm[t] = 16.f / (1.f + __expf(-v)) + mask[w * 4096 + ij];
}

// ---------------------------------------------------------------------------
// Kernel 2/4: fp16 mma.sync GEMM (fp32 accumulate), templated output type.
// C[m][n] = sum_k A[m][k]*B[n][k] + bias[n]; A: MxK, B: NxK row-major fp16.
// Block tile 128x128, K-tile 64 halves, 128 threads = 4 warps (2m x 2n),
// warp tile 64x64, m16n8k16, 3-stage cp.async pipeline, XOR-16B swizzle,
// ldmatrix.x4 with REGISTER DOUBLE-BUFFERED fragments (k-step ks+1 loads
// issue before k-step ks MMAs, hiding LDS latency).
// ---------------------------------------------------------------------------
#define BM 128
#define BN 128
#define BKT 64
#define STAGES 3
#define GEMM_SMEM (STAGES * (BM + BN) * BKT * 2)   // 98304 bytes

template <typename OutT>
__global__ __launch_bounds__(128, 2)
void gemm_f16_abT(const __half* __restrict__ A, const __half* __restrict__ B,
                  const float* __restrict__ bias, OutT* __restrict__ C,
                  int M, int N, int K)
{
    extern __shared__ __half smh[];
    __half* AsBase = smh;
    __half* BsBase = smh + STAGES * BM * BKT;
    const uint32_t smemA_u32 = (uint32_t)__cvta_generic_to_shared(AsBase);
    const uint32_t smemB_u32 = (uint32_t)__cvta_generic_to_shared(BsBase);

    const int tid  = threadIdx.x;
    const int bm   = blockIdx.y * BM;
    const int bn   = blockIdx.x * BN;
    const int warp = tid >> 5;
    const int lane = tid & 31;
    const int wm   = (warp & 1) * 64;
    const int wn   = (warp >> 1) * 64;
    const int g    = lane >> 2;
    const int t4   = lane & 3;

    // ldmatrix lane decomposition (chunk = 8 halves = 16B)
    const int lt = lane >> 3;
    const int lr = lane & 7;
    const int a_row_l = wm + (lt & 1) * 8 + lr;   // + im*16
    const int a_chk_l = lt >> 1;                  // + 2*kstep
    const int b_row_l = wn + (lt >> 1) * 8 + lr;  // + n16*16
    const int b_chk_l = lt & 1;                   // + 2*kstep

    float acc[4][8][4];
#pragma unroll
    for (int im = 0; im < 4; im++)
#pragma unroll
        for (int in = 0; in < 8; in++)
#pragma unroll
            for (int r = 0; r < 4; r++) acc[im][in][r] = 0.f;

    const int NIT = K / BKT;

    auto issue = [&](int stage, int kt) {
        const int kbase = kt * BKT;
#pragma unroll
        for (int l = 0; l < 8; l++) {
            int f    = tid + l * 128;     // 0..1023
            int row  = f >> 3;            // 0..127
            int chk  = f & 7;
            int sc   = (chk ^ (row & 7)) * 8;
            cp16(smemA_u32 + (uint32_t)(stage * BM * BKT + row * BKT + sc) * 2,
                 A + (size_t)(bm + row) * K + kbase + chk * 8);
            cp16(smemB_u32 + (uint32_t)(stage * BN * BKT + row * BKT + sc) * 2,
                 B + (size_t)(bn + row) * K + kbase + chk * 8);
        }
    };

    issue(0, 0); cp_commit();
    issue(1, 1); cp_commit();

    for (int it = 0; it < NIT; it++) {
        const int s = it % STAGES;
        cp_wait<1>();
        __syncthreads();

        if (it + 2 < NIT) issue((it + 2) % STAGES, it + 2);
        cp_commit();

        const __half* Ast = AsBase + s * BM * BKT;
        const __half* Bst = BsBase + s * BN * BKT;

        // register-double-buffered fragments
        uint32_t af[2][4][4], bf[2][16];

        auto ldfrag = [&](int buf, int kc) {
#pragma unroll
            for (int im = 0; im < 4; im++) {
                int row = a_row_l + im * 16;
                int chk = kc + a_chk_l;
                ldsm_x4(af[buf][im], Ast + row * BKT + ((chk ^ (row & 7)) * 8));
            }
#pragma unroll
            for (int n16 = 0; n16 < 4; n16++) {
                int row = b_row_l + n16 * 16;
                int chk = kc + b_chk_l;
                ldsm_x4(bf[buf] + n16 * 4, Bst + row * BKT + ((chk ^ (row & 7)) * 8));
            }
        };

        ldfrag(0, 0);
#pragma unroll
        for (int ks = 0; ks < 4; ks++) {
            const int cur = ks & 1;
            if (ks < 3) ldfrag(cur ^ 1, (ks + 1) * 2);
#pragma unroll
            for (int im = 0; im < 4; im++)
#pragma unroll
                for (int in = 0; in < 8; in++)
                    mma_f16(acc[im][in], af[cur][im], bf[cur] + in * 2);
        }
    }

    // epilogue
#pragma unroll
    for (int im = 0; im < 4; im++) {
#pragma unroll
        for (int in = 0; in < 8; in++) {
            int r = bm + wm + im * 16 + g;
            int c = bn + wn + in * 8 + t4 * 2;
            float b0 = bias[c];
            float b1 = bias[c + 1];
            float v00 = acc[im][in][0] + b0, v01 = acc[im][in][1] + b1;
            float v10 = acc[im][in][2] + b0, v11 = acc[im][in][3] + b1;
            if constexpr (sizeof(OutT) == 4) {
                *(float2*)((float*)C + (size_t)r * N + c)       = make_float2(v00, v01);
                *(float2*)((float*)C + (size_t)(r + 8) * N + c) = make_float2(v10, v11);
            } else {
                *(__half2*)((__half*)C + (size_t)r * N + c)       = __floats2half2_rn(v00, v01);
                *(__half2*)((__half*)C + (size_t)(r + 8) * N + c) = __floats2half2_rn(v10, v11);
            }
        }
    }
}

// ---------------------------------------------------------------------------
// Kernel 3: tensor-core attention. One block (128 thr, 4 warps) per (b,h).
// bias+mask prefetched into registers BEFORE the S-phase MMAs.
// ---------------------------------------------------------------------------
__global__ __launch_bounds__(128)
void attn_mma_kernel(__half* __restrict__ out)
{
    const int bh = blockIdx.x;
    const int b  = bh >> 4;
    const int h  = bh & 15;
    const int w  = b % NW;

    __shared__ __half Qs[64][40];
    __shared__ __half Ks[64][40];
    __shared__ __half Vs[64][40];

    const int tid  = threadIdx.x;
    const int warp = tid >> 5;
    const int lane = tid & 31;

    {
        const __half* base = g_qkvh + (size_t)b * NTOK * QKVN + h * HD;
        int tok = tid >> 1;
        int p   = tid & 1;
        const uint4* qp = (const uint4*)(base + (size_t)tok * QKVN);
        const uint4* kp = (const uint4*)(base + (size_t)tok * QKVN + 512);
        const uint4* vp = (const uint4*)(base + (size_t)tok * QKVN + 1024);
        *(uint4*)&Qs[tok][p * 16 + 0] = qp[p * 2 + 0];
        *(uint4*)&Qs[tok][p * 16 + 8] = qp[p * 2 + 1];
        *(uint4*)&Ks[tok][p * 16 + 0] = kp[p * 2 + 0];
        *(uint4*)&Ks[tok][p * 16 + 8] = kp[p * 2 + 1];
        *(uint4*)&Vs[tok][p * 16 + 0] = vp[p * 2 + 0];
        *(uint4*)&Vs[tok][p * 16 + 8] = vp[p * 2 + 1];
    }
    __syncthreads();

    {
        int r = tid & 63;
        __half* row = (tid < 64) ? Qs[r] : Ks[r];
        float f[32];
        float s = 0.f;
#pragma unroll
        for (int i = 0; i < 16; i++) {
            float2 v = __half22float2(*(__half2*)&row[i * 2]);
            f[i * 2] = v.x; f[i * 2 + 1] = v.y;
            s += v.x * v.x + v.y * v.y;
        }
        float inv = 1.0f / fmaxf(sqrtf(s), 1e-12f);
        if (tid < 64) inv *= g_scale[h];
#pragma unroll
        for (int i = 0; i < 16; i++)
            *(__half2*)&row[i * 2] = __floats2half2_rn(f[i * 2] * inv, f[i * 2 + 1] * inv);
    }
    __syncthreads();

    const int lt = lane >> 3;
    const int lr = lane & 7;
    const int g  = lane >> 2;
    const int t4 = lane & 3;
    const int r0 = warp * 16;
    const int r_lo = r0 + g;
    const int r_hi = r0 + 8 + g;

    // ---- prefetch bias+mask into registers (overlaps with S MMAs below) ----
    const float* bmp = g_bm + (((size_t)h * NW + w) << 12);
    float2 blo[8], bhi[8];
#pragma unroll
    for (int t = 0; t < 8; t++) {
        int col = t * 8 + t4 * 2;
        blo[t] = *(const float2*)&bmp[r_lo * 64 + col];
        bhi[t] = *(const float2*)&bmp[r_hi * 64 + col];
    }

    // ---- S = Qn Kn^T (this warp's 16 rows x 64 cols) ----
    float sacc[8][4];
#pragma unroll
    for (int t = 0; t < 8; t++)
#pragma unroll
        for (int r = 0; r < 4; r++) sacc[t][r] = 0.f;

#pragma unroll
    for (int ks = 0; ks < 2; ks++) {
        uint32_t af[4];
        ldsm_x4(af, &Qs[r0 + (lt & 1) * 8 + lr][(lt >> 1) * 8 + ks * 16]);
#pragma unroll
        for (int ng = 0; ng < 4; ng++) {
            uint32_t bfk[4];
            ldsm_x4(bfk, &Ks[ng * 16 + (lt >> 1) * 8 + lr][(lt & 1) * 8 + ks * 16]);
            mma_f16(sacc[ng * 2 + 0], af, bfk);
            mma_f16(sacc[ng * 2 + 1], af, bfk + 2);
        }
    }

    // ---- add prefetched bias+mask, softmax in registers ----
#pragma unroll
    for (int t = 0; t < 8; t++) {
        sacc[t][0] += blo[t].x; sacc[t][1] += blo[t].y;
        sacc[t][2] += bhi[t].x; sacc[t][3] += bhi[t].y;
    }

    float mlo = -1e30f, mhi = -1e30f;
#pragma unroll
    for (int t = 0; t < 8; t++) {
        mlo = fmaxf(mlo, fmaxf(sacc[t][0], sacc[t][1]));
        mhi = fmaxf(mhi, fmaxf(sacc[t][2], sacc[t][3]));
    }
    mlo = fmaxf(mlo, __shfl_xor_sync(0xffffffffu, mlo, 1));
    mlo = fmaxf(mlo, __shfl_xor_sync(0xffffffffu, mlo, 2));
    mhi = fmaxf(mhi, __shfl_xor_sync(0xffffffffu, mhi, 1));
    mhi = fmaxf(mhi, __shfl_xor_sync(0xffffffffu, mhi, 2));

    float slo = 0.f, shi = 0.f;
#pragma unroll
    for (int t = 0; t < 8; t++) {
        sacc[t][0] = __expf(sacc[t][0] - mlo);
        sacc[t][1] = __expf(sacc[t][1] - mlo);
        sacc[t][2] = __expf(sacc[t][2] - mhi);
        sacc[t][3] = __expf(sacc[t][3] - mhi);
        slo += sacc[t][0] + sacc[t][1];
        shi += sacc[t][2] + sacc[t][3];
    }
    slo += __shfl_xor_sync(0xffffffffu, slo, 1);
    slo += __shfl_xor_sync(0xffffffffu, slo, 2);
    shi += __shfl_xor_sync(0xffffffffu, shi, 1);
    shi += __shfl_xor_sync(0xffffffffu, shi, 2);
    const float ilo = 1.0f / slo;
    const float ihi = 1.0f / shi;

    uint32_t p01[8], p23[8];
#pragma unroll
    for (int t = 0; t < 8; t++) {
        p01[t] = h2_as_u32(__floats2half2_rn(sacc[t][0] * ilo, sacc[t][1] * ilo));
        p23[t] = h2_as_u32(__floats2half2_rn(sacc[t][2] * ihi, sacc[t][3] * ihi));
    }

    float oacc[4][4];
#pragma unroll
    for (int t = 0; t < 4; t++)
#pragma unroll
        for (int r = 0; r < 4; r++) oacc[t][r] = 0.f;

#pragma unroll
    for (int kg = 0; kg < 4; kg++) {
        uint32_t af[4] = { p01[kg * 2], p23[kg * 2], p01[kg * 2 + 1], p23[kg * 2 + 1] };
        uint32_t bf0[4], bf1[4];
        ldsm_x4_trans(bf0, &Vs[kg * 16 + (lt & 1) * 8 + lr][(lt >> 1) * 8]);
        ldsm_x4_trans(bf1, &Vs[kg * 16 + (lt & 1) * 8 + lr][(lt >> 1) * 8 + 16]);
        mma_f16(oacc[0], af, bf0);
        mma_f16(oacc[1], af, bf0 + 2);
        mma_f16(oacc[2], af, bf1);
        mma_f16(oacc[3], af, bf1 + 2);
    }

    __half* ob = out + ((size_t)b * NTOK) * CDIM + h * HD;
#pragma unroll
    for (int t = 0; t < 4; t++) {
        int col = t * 8 + t4 * 2;
        *(__half2*)(ob + (size_t)r_lo * CDIM + col) = __floats2half2_rn(oacc[t][0], oacc[t][1]);
        *(__half2*)(ob + (size_t)r_hi * CDIM + col) = __floats2half2_rn(oacc[t][2], oacc[t][3]);
    }
}

// ---------------------------------------------------------------------------
// Launch
// ---------------------------------------------------------------------------
extern "C" void kernel_launch(void* const* d_in, const int* in_sizes, int n_in,
                              void* d_out, int out_size)
{
    const float* x        = (const float*)d_in[0];
    const float* mask     = (const float*)d_in[1];
    const float* qkv_w    = (const float*)d_in[2];
    const float* qkv_b    = (const float*)d_in[3];
    const float* proj_w   = (const float*)d_in[4];
    const float* proj_b   = (const float*)d_in[5];
    const float* t_scale  = (const float*)d_in[6];
    const float* crpb_w1  = (const float*)d_in[7];
    const float* crpb_b1  = (const float*)d_in[8];
    const float* crpb_w2  = (const float*)d_in[9];
    const float* ctable   = (const float*)d_in[10];
    const int*   rel_idx  = (const int*)d_in[11];
    float*       out      = (float*)d_out;

    __half *qkvh, *att, *xh, *wq, *wp;
    cudaGetSymbolAddress((void**)&qkvh, g_qkvh);
    cudaGetSymbolAddress((void**)&att,  g_att);
    cudaGetSymbolAddress((void**)&xh,   g_x);
    cudaGetSymbolAddress((void**)&wq,   g_wq);
    cudaGetSymbolAddress((void**)&wp,   g_wp);

    static bool attr_set = false;
    if (!attr_set) {
        cudaFuncSetAttribute(gemm_f16_abT<__half>,
                             cudaFuncAttributeMaxDynamicSharedMemorySize, GEMM_SMEM);
        cudaFuncSetAttribute(gemm_f16_abT<float>,
                             cudaFuncAttributeMaxDynamicSharedMemorySize, GEMM_SMEM);
        attr_set = true;
    }

    // 1. CRPB table + scale, fused bias+mask fill
    crpb_tbl_kernel<<<1, 256>>>(ctable, crpb_w1, crpb_b1, crpb_w2, t_scale);
    bm_fill_kernel<<<(HEADS * NW * 4096) / 256, 256>>>(rel_idx, mask);

    // 1b. convert GEMM operands to fp16
    {
        int n4x = MTOT * CDIM / 4;
        to_half_kernel<<<(n4x + 255) / 256, 256>>>(x, xh, n4x);
        int n4q = QKVN * CDIM / 4;
        to_half_kernel<<<(n4q + 255) / 256, 256>>>(qkv_w, wq, n4q);
        int n4p = CDIM * CDIM / 4;
        to_half_kernel<<<(n4p + 255) / 256, 256>>>(proj_w, wp, n4p);
    }

    // 2. QKV projection -> fp16
    {
        dim3 grid(QKVN / BN, MTOT / BM);
        gemm_f16_abT<__half><<<grid, 128, GEMM_SMEM>>>(xh, wq, qkv_b, qkvh, MTOT, QKVN, CDIM);
    }

    // 3. tensor-core attention (fp16 in/out)
    attn_mma_kernel<<<BATCH * HEADS, 128>>>(att);

    // 4. output projection -> fp32 d_out
    {
        dim3 grid(CDIM / BN, MTOT / BM);
        gemm_f16_abT<float><<<grid, 128, GEMM_SMEM>>>(att, wp, proj_b, out, MTOT, CDIM, CDIM);
    }
}